// round 8
// baseline (speedup 1.0000x reference)
#include <cuda_runtime.h>
#include <cfloat>
#include <math.h>

#define NB    8
#define NLQ   512
#define NLK   2048
#define NE    512
#define NH    8
#define NHD   64
#define NTOPK 20

// Scratch (allocation-free rule: __device__ globals)
__device__ float g_Q[(size_t)NB * NLQ * NE];             // 8 MB
__device__ float g_K[(size_t)NB * NLK * NE];             // 32 MB
__device__ float g_V[(size_t)NB * NLK * NE];             // 32 MB
__device__ float g_S[(size_t)NB * NH * NLQ * NLK];       // 256 MB
__device__ float g_O[(size_t)NB * NLQ * NE];             // 8 MB

// ----------------------------------------------------------------------------
// C[m,n] = alpha * sum_k A[m,k] * Bw[n,k]   (+ optional bias[n] + resid[m,n])
// 128x128 tile, BK=16, 256 threads, 8x8 microtile. All dims multiples of 128/16.
// Batched via blockIdx.z with (b,h)-decomposed strides (hdiv = H for scores).
// ----------------------------------------------------------------------------
__global__ __launch_bounds__(256, 2)
void sgemm_atb(const float* __restrict__ A, const float* __restrict__ Bw,
               float* __restrict__ C,
               int K, int lda, int ldb, int ldc, float alpha,
               size_t sAb, size_t sAh, size_t sBb, size_t sBh, size_t sCz, int hdiv,
               const float* __restrict__ bias, const float* __restrict__ resid)
{
    __shared__ float As[16][132];
    __shared__ float Bs[16][132];

    const int tid = threadIdx.x;
    const int tx  = tid & 15;
    const int ty  = tid >> 4;
    const int rowBase = blockIdx.y * 128;
    const int colBase = blockIdx.x * 128;

    const int z  = blockIdx.z;
    const int zb = z / hdiv;
    const int zh = z - zb * hdiv;
    A  += (size_t)zb * sAb + (size_t)zh * sAh;
    Bw += (size_t)zb * sBb + (size_t)zh * sBh;
    C  += (size_t)z * sCz;

    float acc[8][8];
    #pragma unroll
    for (int i = 0; i < 8; i++)
        #pragma unroll
        for (int j = 0; j < 8; j++) acc[i][j] = 0.f;

    for (int k0 = 0; k0 < K; k0 += 16) {
        #pragma unroll
        for (int it = 0; it < 2; it++) {
            int f  = tid + (it << 8);     // float4 id, 0..511
            int r  = f >> 2;              // 0..127
            int kq = (f & 3) << 2;        // 0,4,8,12
            float4 va = *reinterpret_cast<const float4*>(A  + (size_t)(rowBase + r) * lda + k0 + kq);
            As[kq + 0][r] = va.x; As[kq + 1][r] = va.y; As[kq + 2][r] = va.z; As[kq + 3][r] = va.w;
            float4 vb = *reinterpret_cast<const float4*>(Bw + (size_t)(colBase + r) * ldb + k0 + kq);
            Bs[kq + 0][r] = vb.x; Bs[kq + 1][r] = vb.y; Bs[kq + 2][r] = vb.z; Bs[kq + 3][r] = vb.w;
        }
        __syncthreads();

        #pragma unroll
        for (int kk = 0; kk < 16; kk++) {
            float a[8], b[8];
            float4 t;
            t = *reinterpret_cast<const float4*>(&As[kk][ty * 4]);      a[0]=t.x; a[1]=t.y; a[2]=t.z; a[3]=t.w;
            t = *reinterpret_cast<const float4*>(&As[kk][ty * 4 + 64]); a[4]=t.x; a[5]=t.y; a[6]=t.z; a[7]=t.w;
            t = *reinterpret_cast<const float4*>(&Bs[kk][tx * 4]);      b[0]=t.x; b[1]=t.y; b[2]=t.z; b[3]=t.w;
            t = *reinterpret_cast<const float4*>(&Bs[kk][tx * 4 + 64]); b[4]=t.x; b[5]=t.y; b[6]=t.z; b[7]=t.w;
            #pragma unroll
            for (int i = 0; i < 8; i++)
                #pragma unroll
                for (int j = 0; j < 8; j++) acc[i][j] = fmaf(a[i], b[j], acc[i][j]);
        }
        __syncthreads();
    }

    #pragma unroll
    for (int i = 0; i < 8; i++) {
        int m = rowBase + ty * 4 + ((i < 4) ? i : 60 + i);  // rows ty*4+{0..3}, ty*4+64+{0..3}
        #pragma unroll
        for (int jj = 0; jj < 2; jj++) {
            int n = colBase + tx * 4 + jj * 64;
            float4 o;
            o.x = alpha * acc[i][jj * 4 + 0];
            o.y = alpha * acc[i][jj * 4 + 1];
            o.z = alpha * acc[i][jj * 4 + 2];
            o.w = alpha * acc[i][jj * 4 + 3];
            if (bias) {
                float4 bb = *reinterpret_cast<const float4*>(bias + n);
                o.x += bb.x; o.y += bb.y; o.z += bb.z; o.w += bb.w;
            }
            if (resid) {
                float4 rr = *reinterpret_cast<const float4*>(resid + (size_t)m * ldc + n);
                o.x += rr.x; o.y += rr.y; o.z += rr.z; o.w += rr.w;
            }
            *reinterpret_cast<float4*>(C + (size_t)m * ldc + n) = o;
        }
    }
}

// ----------------------------------------------------------------------------
// One block (256 threads) per (b,h,q) row of scores:
//   full-row max & sum(exp) -> top-20 of logits -> p = exp(s-m)/sum -> AV gather.
// top_k(softmax(s)) == top_k(s), so no softmax materialization needed.
// ----------------------------------------------------------------------------
__global__ __launch_bounds__(256)
void softmax_topk_av()
{
    const int tid = threadIdx.x;
    const int row = blockIdx.x;            // (b*H + h)*LQ + q
    const int q   = row & (NLQ - 1);
    const int bh  = row >> 9;              // LQ = 512
    const int h   = bh & (NH - 1);
    const int b   = bh >> 3;

    const float* s = g_S + (size_t)row * NLK;

    float sc[8];
    #pragma unroll
    for (int i = 0; i < 8; i++) sc[i] = s[tid + (i << 8)];   // coalesced

    __shared__ float red[256];
    __shared__ int   redi[8];
    __shared__ int   bcastI;
    __shared__ int   topI[NTOPK];
    __shared__ float topP[NTOPK];

    const int lane = tid & 31;
    const int wid  = tid >> 5;

    // ---- row max ----
    float m = sc[0];
    #pragma unroll
    for (int i = 1; i < 8; i++) m = fmaxf(m, sc[i]);
    #pragma unroll
    for (int off = 16; off > 0; off >>= 1)
        m = fmaxf(m, __shfl_xor_sync(0xffffffffu, m, off));
    if (lane == 0) red[wid] = m;
    __syncthreads();
    m = red[0];
    #pragma unroll
    for (int w = 1; w < 8; w++) m = fmaxf(m, red[w]);
    __syncthreads();

    // ---- row sum(exp) ----
    float lsum = 0.f;
    #pragma unroll
    for (int i = 0; i < 8; i++) lsum += expf(sc[i] - m);
    #pragma unroll
    for (int off = 16; off > 0; off >>= 1)
        lsum += __shfl_xor_sync(0xffffffffu, lsum, off);
    if (lane == 0) red[wid] = lsum;
    __syncthreads();
    float denom = red[0];
    #pragma unroll
    for (int w = 1; w < 8; w++) denom += red[w];
    __syncthreads();

    // ---- top-20 (iterative block argmax, 2 barriers/iter) ----
    for (int t = 0; t < NTOPK; t++) {
        float bv = sc[0];
        int   bi = tid;                    // key index = tid + slot*256
        #pragma unroll
        for (int i = 1; i < 8; i++)
            if (sc[i] > bv) { bv = sc[i]; bi = tid + (i << 8); }
        #pragma unroll
        for (int off = 16; off > 0; off >>= 1) {
            float ov = __shfl_down_sync(0xffffffffu, bv, off);
            int   oi = __shfl_down_sync(0xffffffffu, bi, off);
            if (ov > bv || (ov == bv && oi < bi)) { bv = ov; bi = oi; }
        }
        if (lane == 0) { red[wid] = bv; redi[wid] = bi; }
        __syncthreads();
        if (tid == 0) {
            float v = red[0]; int ix = redi[0];
            #pragma unroll
            for (int w = 1; w < 8; w++)
                if (red[w] > v || (red[w] == v && redi[w] < ix)) { v = red[w]; ix = redi[w]; }
            topI[t]  = ix;
            topP[t]  = expf(v - m) / denom;
            bcastI   = ix;
        }
        __syncthreads();
        const int widx = bcastI;
        if ((widx & 255) == tid) {
            const int slot = widx >> 8;
            #pragma unroll
            for (int i = 0; i < 8; i++) if (i == slot) sc[i] = -FLT_MAX;
        }
        // next iteration's red/redi writes are ordered by the two barriers above
    }

    // ---- sparse AV: out[d] = sum_j p_j * V[b, idx_j, h*64+d] ----
    const int d = tid & 63;
    const int g = tid >> 6;                // 4 groups of 5 indices each
    const float* Vb = g_V + (size_t)b * NLK * NE + h * NHD + d;
    float a = 0.f;
    for (int j = g; j < NTOPK; j += 4)
        a = fmaf(topP[j], Vb[(size_t)topI[j] * NE], a);
    red[tid] = a;
    __syncthreads();
    if (g == 0)
        g_O[(size_t)(b * NLQ + q) * NE + h * NHD + d] =
            red[tid] + red[tid + 64] + red[tid + 128] + red[tid + 192];
}

// ----------------------------------------------------------------------------
extern "C" void kernel_launch(void* const* d_in, const int* in_sizes, int n_in,
                              void* d_out, int out_size)
{
    const float* q  = (const float*)d_in[0];
    const float* k  = (const float*)d_in[1];
    const float* v  = (const float*)d_in[2];
    const float* Wq = (const float*)d_in[3];
    const float* Wk = (const float*)d_in[4];
    const float* Wv = (const float*)d_in[5];
    const float* Wo = (const float*)d_in[6];
    const float* bo = (const float*)d_in[7];
    float* out = (float*)d_out;

    float *gQ, *gK, *gV, *gS, *gO;
    cudaGetSymbolAddress((void**)&gQ, g_Q);
    cudaGetSymbolAddress((void**)&gK, g_K);
    cudaGetSymbolAddress((void**)&gV, g_V);
    cudaGetSymbolAddress((void**)&gS, g_S);
    cudaGetSymbolAddress((void**)&gO, g_O);

    dim3 blk(256);

    // Q = q @ Wq^T : [4096,512] x [512,512]^T
    sgemm_atb<<<dim3(NE / 128, (NB * NLQ) / 128, 1), blk>>>(
        q, Wq, gQ, NE, NE, NE, NE, 1.0f,
        0, 0, 0, 0, 0, 1, nullptr, nullptr);

    // K = k @ Wk^T : [16384,512]
    sgemm_atb<<<dim3(NE / 128, (NB * NLK) / 128, 1), blk>>>(
        k, Wk, gK, NE, NE, NE, NE, 1.0f,
        0, 0, 0, 0, 0, 1, nullptr, nullptr);

    // V = v @ Wv^T : [16384,512]
    sgemm_atb<<<dim3(NE / 128, (NB * NLK) / 128, 1), blk>>>(
        v, Wv, gV, NE, NE, NE, NE, 1.0f,
        0, 0, 0, 0, 0, 1, nullptr, nullptr);

    // S[b,h] = (1/8) * Q_h @ K_h^T : per (b,h): [512,64] x [2048,64]^T
    sgemm_atb<<<dim3(NLK / 128, NLQ / 128, NB * NH), blk>>>(
        gQ, gK, gS, NHD, NE, NE, NLK, 0.125f,
        (size_t)NLQ * NE, (size_t)NHD,          // A strides (b, h)
        (size_t)NLK * NE, (size_t)NHD,          // B strides (b, h)
        (size_t)NLQ * NLK, NH,                  // C stride per z, hdiv
        nullptr, nullptr);

    // softmax + top-20 + sparse AV
    softmax_topk_av<<<NB * NH * NLQ, blk>>>();

    // out = O @ Wo^T + bo + q
    sgemm_atb<<<dim3(NE / 128, (NB * NLQ) / 128, 1), blk>>>(
        gO, Wo, out, NE, NE, NE, NE, 1.0f,
        0, 0, 0, 0, 0, 1, bo, q);
}

// round 9
// speedup vs baseline: 1.0146x; 1.0146x over previous
#include <cuda_runtime.h>
#include <cfloat>
#include <math.h>

#define NB    8
#define NLQ   512
#define NLK   2048
#define NE    512
#define NH    8
#define NHD   64
#define NTOPK 20

// Scratch (allocation-free rule: __device__ globals)
__device__ float g_Q[(size_t)NB * NLQ * NE];             // 8 MB
__device__ float g_K[(size_t)NB * NLK * NE];             // 32 MB
__device__ float g_V[(size_t)NB * NLK * NE];             // 32 MB
__device__ float g_S[(size_t)NB * NH * NLQ * NLK];       // 256 MB
__device__ float g_O[(size_t)NB * NLQ * NE];             // 8 MB

// ----------------------------------------------------------------------------
// C[m,n] = alpha * sum_k A[m,k] * Bw[n,k]   (+ optional bias[n] + resid[m,n])
// 128x128 tile, BK=16, 256 threads, 8x8 microtile, software-pipelined:
// next K-tile is prefetched into registers while current tile computes.
// Batched via blockIdx.z with (b,h)-decomposed strides (hdiv = H for scores).
// ----------------------------------------------------------------------------
__global__ __launch_bounds__(256, 2)
void sgemm_atb(const float* __restrict__ A, const float* __restrict__ Bw,
               float* __restrict__ C,
               int K, int lda, int ldb, int ldc, float alpha,
               size_t sAb, size_t sAh, size_t sBb, size_t sBh, size_t sCz, int hdiv,
               const float* __restrict__ bias, const float* __restrict__ resid)
{
    __shared__ float As[16][132];
    __shared__ float Bs[16][132];

    const int tid = threadIdx.x;
    const int tx  = tid & 15;
    const int ty  = tid >> 4;
    const int rowBase = blockIdx.y * 128;
    const int colBase = blockIdx.x * 128;

    const int z  = blockIdx.z;
    const int zb = z / hdiv;
    const int zh = z - zb * hdiv;
    A  += (size_t)zb * sAb + (size_t)zh * sAh;
    Bw += (size_t)zb * sBb + (size_t)zh * sBh;
    C  += (size_t)z * sCz;

    // per-thread global load coordinates (two float4 loads per matrix)
    int lr[2], lk[2];
    #pragma unroll
    for (int it = 0; it < 2; it++) {
        int f = tid + (it << 8);
        lr[it] = f >> 2;
        lk[it] = (f & 3) << 2;
    }

    float acc[8][8];
    #pragma unroll
    for (int i = 0; i < 8; i++)
        #pragma unroll
        for (int j = 0; j < 8; j++) acc[i][j] = 0.f;

    float4 pa[2], pb[2];

    // prologue: load tile 0
    #pragma unroll
    for (int it = 0; it < 2; it++) {
        pa[it] = *reinterpret_cast<const float4*>(A  + (size_t)(rowBase + lr[it]) * lda + lk[it]);
        pb[it] = *reinterpret_cast<const float4*>(Bw + (size_t)(colBase + lr[it]) * ldb + lk[it]);
    }
    #pragma unroll
    for (int it = 0; it < 2; it++) {
        As[lk[it] + 0][lr[it]] = pa[it].x; As[lk[it] + 1][lr[it]] = pa[it].y;
        As[lk[it] + 2][lr[it]] = pa[it].z; As[lk[it] + 3][lr[it]] = pa[it].w;
        Bs[lk[it] + 0][lr[it]] = pb[it].x; Bs[lk[it] + 1][lr[it]] = pb[it].y;
        Bs[lk[it] + 2][lr[it]] = pb[it].z; Bs[lk[it] + 3][lr[it]] = pb[it].w;
    }
    __syncthreads();

    for (int k0 = 0; k0 < K; k0 += 16) {
        const bool has = (k0 + 16) < K;
        if (has) {
            #pragma unroll
            for (int it = 0; it < 2; it++) {
                pa[it] = *reinterpret_cast<const float4*>(A  + (size_t)(rowBase + lr[it]) * lda + k0 + 16 + lk[it]);
                pb[it] = *reinterpret_cast<const float4*>(Bw + (size_t)(colBase + lr[it]) * ldb + k0 + 16 + lk[it]);
            }
        }

        #pragma unroll
        for (int kk = 0; kk < 16; kk++) {
            float a[8], b[8];
            float4 t;
            t = *reinterpret_cast<const float4*>(&As[kk][ty * 4]);      a[0]=t.x; a[1]=t.y; a[2]=t.z; a[3]=t.w;
            t = *reinterpret_cast<const float4*>(&As[kk][ty * 4 + 64]); a[4]=t.x; a[5]=t.y; a[6]=t.z; a[7]=t.w;
            t = *reinterpret_cast<const float4*>(&Bs[kk][tx * 4]);      b[0]=t.x; b[1]=t.y; b[2]=t.z; b[3]=t.w;
            t = *reinterpret_cast<const float4*>(&Bs[kk][tx * 4 + 64]); b[4]=t.x; b[5]=t.y; b[6]=t.z; b[7]=t.w;
            #pragma unroll
            for (int i = 0; i < 8; i++)
                #pragma unroll
                for (int j = 0; j < 8; j++) acc[i][j] = fmaf(a[i], b[j], acc[i][j]);
        }
        __syncthreads();

        if (has) {
            #pragma unroll
            for (int it = 0; it < 2; it++) {
                As[lk[it] + 0][lr[it]] = pa[it].x; As[lk[it] + 1][lr[it]] = pa[it].y;
                As[lk[it] + 2][lr[it]] = pa[it].z; As[lk[it] + 3][lr[it]] = pa[it].w;
                Bs[lk[it] + 0][lr[it]] = pb[it].x; Bs[lk[it] + 1][lr[it]] = pb[it].y;
                Bs[lk[it] + 2][lr[it]] = pb[it].z; Bs[lk[it] + 3][lr[it]] = pb[it].w;
            }
            __syncthreads();
        }
    }

    #pragma unroll
    for (int i = 0; i < 8; i++) {
        int m = rowBase + ty * 4 + ((i < 4) ? i : 60 + i);  // rows ty*4+{0..3}, ty*4+64+{0..3}
        #pragma unroll
        for (int jj = 0; jj < 2; jj++) {
            int n = colBase + tx * 4 + jj * 64;
            float4 o;
            o.x = alpha * acc[i][jj * 4 + 0];
            o.y = alpha * acc[i][jj * 4 + 1];
            o.z = alpha * acc[i][jj * 4 + 2];
            o.w = alpha * acc[i][jj * 4 + 3];
            if (bias) {
                float4 bb = *reinterpret_cast<const float4*>(bias + n);
                o.x += bb.x; o.y += bb.y; o.z += bb.z; o.w += bb.w;
            }
            if (resid) {
                float4 rr = *reinterpret_cast<const float4*>(resid + (size_t)m * ldc + n);
                o.x += rr.x; o.y += rr.y; o.z += rr.z; o.w += rr.w;
            }
            *reinterpret_cast<float4*>(C + (size_t)m * ldc + n) = o;
        }
    }
}

// ----------------------------------------------------------------------------
// One block (256 threads, 8 warps) per (b,h,q) row of scores.
//   row max & sum(exp) (2 barriers), then each warp selects top-20 of its
//   256-element chunk via barrier-free warp argmax (20 iters, shfl-only),
//   warp 0 merges 160 candidates -> global top-20 -> probs -> sparse AV.
// top_k(softmax(s)) == top_k(s), so no softmax materialization needed.
// ----------------------------------------------------------------------------
__global__ __launch_bounds__(256)
void softmax_topk_av()
{
    const int tid  = threadIdx.x;
    const int lane = tid & 31;
    const int wid  = tid >> 5;             // 0..7
    const int row  = blockIdx.x;           // (b*H + h)*LQ + q
    const int q    = row & (NLQ - 1);
    const int bh   = row >> 9;             // LQ = 512
    const int h    = bh & (NH - 1);
    const int b    = bh >> 3;

    const float* s = g_S + (size_t)row * NLK;
    const int base = wid << 8;             // this warp's 256-element chunk

    float v[8];
    #pragma unroll
    for (int i = 0; i < 8; i++) v[i] = s[base + lane + (i << 5)];   // coalesced

    __shared__ float smax[8];
    __shared__ float ssum[8];
    __shared__ float candV[8 * NTOPK];
    __shared__ int   candI[8 * NTOPK];
    __shared__ int   topI[NTOPK];
    __shared__ float topP[NTOPK];
    __shared__ float red[256];

    // ---- row max ----
    float m = v[0];
    #pragma unroll
    for (int i = 1; i < 8; i++) m = fmaxf(m, v[i]);
    #pragma unroll
    for (int off = 16; off > 0; off >>= 1)
        m = fmaxf(m, __shfl_xor_sync(0xffffffffu, m, off));
    if (lane == 0) smax[wid] = m;
    __syncthreads();
    float gm = smax[0];
    #pragma unroll
    for (int w = 1; w < 8; w++) gm = fmaxf(gm, smax[w]);

    // ---- row sum(exp) ----
    float ls = 0.f;
    #pragma unroll
    for (int i = 0; i < 8; i++) ls += expf(v[i] - gm);
    #pragma unroll
    for (int off = 16; off > 0; off >>= 1)
        ls += __shfl_xor_sync(0xffffffffu, ls, off);
    if (lane == 0) ssum[wid] = ls;
    __syncthreads();
    float denom = ssum[0];
    #pragma unroll
    for (int w = 1; w < 8; w++) denom += ssum[w];

    // ---- per-warp top-20 (barrier-free) ----
    #pragma unroll 1
    for (int t = 0; t < NTOPK; t++) {
        float bv = v[0];
        int   bs = 0;
        #pragma unroll
        for (int i = 1; i < 8; i++)
            if (v[i] > bv) { bv = v[i]; bs = i; }
        int bidx = base + lane + (bs << 5);
        #pragma unroll
        for (int off = 16; off > 0; off >>= 1) {
            float ov = __shfl_xor_sync(0xffffffffu, bv, off);
            int   oi = __shfl_xor_sync(0xffffffffu, bidx, off);
            if (ov > bv || (ov == bv && oi < bidx)) { bv = ov; bidx = oi; }
        }
        // all lanes hold the warp winner; owner invalidates it
        const int rel = bidx - base;
        if (lane == (rel & 31)) {
            const int slot = rel >> 5;
            #pragma unroll
            for (int i = 0; i < 8; i++) if (i == slot) v[i] = -FLT_MAX;
        }
        if (lane == 0) { candV[wid * NTOPK + t] = bv; candI[wid * NTOPK + t] = bidx; }
    }
    __syncthreads();

    // ---- warp 0 merges 160 candidates -> top-20 ----
    if (wid == 0) {
        float cv[5]; int ci[5];
        #pragma unroll
        for (int i = 0; i < 5; i++) { cv[i] = candV[lane + (i << 5)]; ci[i] = candI[lane + (i << 5)]; }
        #pragma unroll 1
        for (int t = 0; t < NTOPK; t++) {
            float bv = cv[0];
            int   bs = 0;
            #pragma unroll
            for (int i = 1; i < 5; i++)
                if (cv[i] > bv) { bv = cv[i]; bs = i; }
            int bidx = (bv == -FLT_MAX) ? 0x7fffffff : ci[bs];
            #pragma unroll
            for (int off = 16; off > 0; off >>= 1) {
                float ov = __shfl_xor_sync(0xffffffffu, bv, off);
                int   oi = __shfl_xor_sync(0xffffffffu, bidx, off);
                if (ov > bv || (ov == bv && oi < bidx)) { bv = ov; bidx = oi; }
            }
            // invalidate winner (key indices are unique -> match by index)
            #pragma unroll
            for (int i = 0; i < 5; i++) if (ci[i] == bidx) cv[i] = -FLT_MAX;
            if (lane == 0) { topI[t] = bidx; topP[t] = expf(bv - gm) / denom; }
        }
    }
    __syncthreads();

    // ---- sparse AV: out[d] = sum_j p_j * V[b, idx_j, h*64+d] ----
    const int d = tid & 63;
    const int g = tid >> 6;                // 4 groups of 5 indices each
    const float* Vb = g_V + (size_t)b * NLK * NE + h * NHD + d;
    float a = 0.f;
    #pragma unroll
    for (int j = g; j < NTOPK; j += 4)
        a = fmaf(topP[j], Vb[(size_t)topI[j] * NE], a);
    red[tid] = a;
    __syncthreads();
    if (g == 0)
        g_O[(size_t)(b * NLQ + q) * NE + h * NHD + d] =
            red[tid] + red[tid + 64] + red[tid + 128] + red[tid + 192];
}

// ----------------------------------------------------------------------------
extern "C" void kernel_launch(void* const* d_in, const int* in_sizes, int n_in,
                              void* d_out, int out_size)
{
    const float* q  = (const float*)d_in[0];
    const float* k  = (const float*)d_in[1];
    const float* v  = (const float*)d_in[2];
    const float* Wq = (const float*)d_in[3];
    const float* Wk = (const float*)d_in[4];
    const float* Wv = (const float*)d_in[5];
    const float* Wo = (const float*)d_in[6];
    const float* bo = (const float*)d_in[7];
    float* out = (float*)d_out;

    float *gQ, *gK, *gV, *gS, *gO;
    cudaGetSymbolAddress((void**)&gQ, g_Q);
    cudaGetSymbolAddress((void**)&gK, g_K);
    cudaGetSymbolAddress((void**)&gV, g_V);
    cudaGetSymbolAddress((void**)&gS, g_S);
    cudaGetSymbolAddress((void**)&gO, g_O);

    dim3 blk(256);

    // Q = q @ Wq^T : [4096,512] x [512,512]^T
    sgemm_atb<<<dim3(NE / 128, (NB * NLQ) / 128, 1), blk>>>(
        q, Wq, gQ, NE, NE, NE, NE, 1.0f,
        0, 0, 0, 0, 0, 1, nullptr, nullptr);

    // K = k @ Wk^T : [16384,512]
    sgemm_atb<<<dim3(NE / 128, (NB * NLK) / 128, 1), blk>>>(
        k, Wk, gK, NE, NE, NE, NE, 1.0f,
        0, 0, 0, 0, 0, 1, nullptr, nullptr);

    // V = v @ Wv^T : [16384,512]
    sgemm_atb<<<dim3(NE / 128, (NB * NLK) / 128, 1), blk>>>(
        v, Wv, gV, NE, NE, NE, NE, 1.0f,
        0, 0, 0, 0, 0, 1, nullptr, nullptr);

    // S[b,h] = (1/8) * Q_h @ K_h^T : per (b,h): [512,64] x [2048,64]^T
    sgemm_atb<<<dim3(NLK / 128, NLQ / 128, NB * NH), blk>>>(
        gQ, gK, gS, NHD, NE, NE, NLK, 0.125f,
        (size_t)NLQ * NE, (size_t)NHD,          // A strides (b, h)
        (size_t)NLK * NE, (size_t)NHD,          // B strides (b, h)
        (size_t)NLQ * NLK, NH,                  // C stride per z, hdiv
        nullptr, nullptr);

    // softmax + top-20 + sparse AV
    softmax_topk_av<<<NB * NH * NLQ, blk>>>();

    // out = O @ Wo^T + bo + q
    sgemm_atb<<<dim3(NE / 128, (NB * NLQ) / 128, 1), blk>>>(
        gO, Wo, out, NE, NE, NE, NE, 1.0f,
        0, 0, 0, 0, 0, 1, bo, q);
}

// round 10
// speedup vs baseline: 1.4040x; 1.3838x over previous
#include <cuda_runtime.h>
#include <cfloat>
#include <math.h>
#include <stdint.h>

#define NB    8
#define NLQ   512
#define NLK   2048
#define NE    512
#define NH    8
#define NHD   64
#define NTOPK 20

// Scratch (allocation-free rule: __device__ globals)
__device__ float g_Q[(size_t)NB * NLQ * NE];             // 8 MB
__device__ float g_K[(size_t)NB * NLK * NE];             // 32 MB
__device__ float g_V[(size_t)NB * NLK * NE];             // 32 MB
__device__ float g_S[(size_t)NB * NH * NLQ * NLK];       // 256 MB
__device__ float g_O[(size_t)NB * NLQ * NE];             // 8 MB

__device__ __forceinline__ float to_tf32(float x) {
    uint32_t u;
    asm("cvt.rna.tf32.f32 %0, %1;" : "=r"(u) : "f"(x));
    return __uint_as_float(u);
}

__device__ __forceinline__ uint32_t smem_u32(const void* p) {
    return (uint32_t)__cvta_generic_to_shared(p);
}

#define LDSM_X4(R0, R1, R2, R3, ADDR)                                          \
    asm volatile("ldmatrix.sync.aligned.m8n8.x4.shared.b16 {%0,%1,%2,%3}, [%4];" \
                 : "=r"(R0), "=r"(R1), "=r"(R2), "=r"(R3) : "r"(ADDR))

#define MMA_TF32(C, A, B0, B1)                                                  \
    asm volatile("mma.sync.aligned.m16n8k8.row.col.f32.tf32.tf32.f32 "          \
                 "{%0,%1,%2,%3}, {%4,%5,%6,%7}, {%8,%9}, {%0,%1,%2,%3};"        \
                 : "+f"((C)[0]), "+f"((C)[1]), "+f"((C)[2]), "+f"((C)[3])       \
                 : "r"((A)[0]), "r"((A)[1]), "r"((A)[2]), "r"((A)[3]),          \
                   "r"(B0), "r"(B1))

// ----------------------------------------------------------------------------
// C[m,n] = alpha * sum_k A[m,k] * Bw[n,k]   (+ optional bias[n] + resid[m,n])
// TF32 tensor-core GEMM: 128x128 block tile, BK=32, 256 threads (8 warps, 2x4),
// warp tile 64x32 via m16n8k8 atoms (4x4). k-major smem, stride 36 floats
// (conflict-free for ldmatrix: 144B row stride spreads across all banks).
// Register-prefetch pipeline over K tiles. Batched via blockIdx.z.
// ----------------------------------------------------------------------------
__global__ __launch_bounds__(256, 2)
void gemm_tf32(const float* __restrict__ A, const float* __restrict__ Bw,
               float* __restrict__ C,
               int K, int lda, int ldb, int ldc, float alpha,
               size_t sAb, size_t sAh, size_t sBb, size_t sBh, size_t sCz, int hdiv,
               const float* __restrict__ bias, const float* __restrict__ resid)
{
    __shared__ float As[128][36];
    __shared__ float Bs[128][36];

    const int tid  = threadIdx.x;
    const int lane = tid & 31;
    const int wid  = tid >> 5;
    const int wm   = wid >> 2;          // 0..1 -> 64 rows each
    const int wn   = wid & 3;           // 0..3 -> 32 cols each
    const int rowBase = blockIdx.y * 128;
    const int colBase = blockIdx.x * 128;

    const int z  = blockIdx.z;
    const int zb = z / hdiv;
    const int zh = z - zb * hdiv;
    A  += (size_t)zb * sAb + (size_t)zh * sAh;
    Bw += (size_t)zb * sBb + (size_t)zh * sBh;
    C  += (size_t)z * sCz;

    // loader coords: 4 float4 per thread per matrix (128 rows x 32 k)
    int lrow[4], lcol[4];
    #pragma unroll
    for (int i = 0; i < 4; i++) {
        int f = tid + (i << 8);
        lrow[i] = f >> 3;
        lcol[i] = (f & 7) << 2;
    }

    // fragment smem byte addresses
    const int arow = wm * 64 + (lane & 15);
    const int acol = (lane >> 4) << 2;
    uint32_t aAddr[4];
    #pragma unroll
    for (int mi = 0; mi < 4; mi++)
        aAddr[mi] = smem_u32(&As[arow + mi * 16][acol]);
    const int brow = wn * 32 + ((lane >> 4) << 3) + (lane & 7);
    const int bcol = ((lane >> 3) & 1) << 2;
    uint32_t bAddr[2];
    #pragma unroll
    for (int p = 0; p < 2; p++)
        bAddr[p] = smem_u32(&Bs[brow + p * 16][bcol]);

    float acc[4][4][4];
    #pragma unroll
    for (int mi = 0; mi < 4; mi++)
        #pragma unroll
        for (int ni = 0; ni < 4; ni++)
            #pragma unroll
            for (int r = 0; r < 4; r++) acc[mi][ni][r] = 0.f;

    float4 pa[4], pb[4];

    // prologue: load K-tile 0
    #pragma unroll
    for (int i = 0; i < 4; i++) {
        pa[i] = *reinterpret_cast<const float4*>(A  + (size_t)(rowBase + lrow[i]) * lda + lcol[i]);
        pb[i] = *reinterpret_cast<const float4*>(Bw + (size_t)(colBase + lrow[i]) * ldb + lcol[i]);
    }
    #pragma unroll
    for (int i = 0; i < 4; i++) {
        float* da = &As[lrow[i]][lcol[i]];
        da[0] = to_tf32(pa[i].x); da[1] = to_tf32(pa[i].y);
        da[2] = to_tf32(pa[i].z); da[3] = to_tf32(pa[i].w);
        float* db = &Bs[lrow[i]][lcol[i]];
        db[0] = to_tf32(pb[i].x); db[1] = to_tf32(pb[i].y);
        db[2] = to_tf32(pb[i].z); db[3] = to_tf32(pb[i].w);
    }
    __syncthreads();

    for (int k0 = 0; k0 < K; k0 += 32) {
        const bool has = (k0 + 32) < K;
        if (has) {
            #pragma unroll
            for (int i = 0; i < 4; i++) {
                pa[i] = *reinterpret_cast<const float4*>(A  + (size_t)(rowBase + lrow[i]) * lda + k0 + 32 + lcol[i]);
                pb[i] = *reinterpret_cast<const float4*>(Bw + (size_t)(colBase + lrow[i]) * ldb + k0 + 32 + lcol[i]);
            }
        }

        #pragma unroll
        for (int ks = 0; ks < 4; ks++) {
            const uint32_t koff = ks * 32;        // 8 floats = 32 bytes
            uint32_t a[4][4], b[2][4];
            #pragma unroll
            for (int mi = 0; mi < 4; mi++)
                LDSM_X4(a[mi][0], a[mi][1], a[mi][2], a[mi][3], aAddr[mi] + koff);
            #pragma unroll
            for (int p = 0; p < 2; p++)
                LDSM_X4(b[p][0], b[p][1], b[p][2], b[p][3], bAddr[p] + koff);
            #pragma unroll
            for (int mi = 0; mi < 4; mi++)
                #pragma unroll
                for (int ni = 0; ni < 4; ni++) {
                    const int p = ni >> 1, o = (ni & 1) << 1;
                    MMA_TF32(acc[mi][ni], a[mi], b[p][o], b[p][o + 1]);
                }
        }
        __syncthreads();

        if (has) {
            #pragma unroll
            for (int i = 0; i < 4; i++) {
                float* da = &As[lrow[i]][lcol[i]];
                da[0] = to_tf32(pa[i].x); da[1] = to_tf32(pa[i].y);
                da[2] = to_tf32(pa[i].z); da[3] = to_tf32(pa[i].w);
                float* db = &Bs[lrow[i]][lcol[i]];
                db[0] = to_tf32(pb[i].x); db[1] = to_tf32(pb[i].y);
                db[2] = to_tf32(pb[i].z); db[3] = to_tf32(pb[i].w);
            }
            __syncthreads();
        }
    }

    // epilogue: c0 (r, c), c1 (r, c+1), c2 (r+8, c), c3 (r+8, c+1)
    const int erow = rowBase + wm * 64 + (lane >> 2);
    const int ecol = colBase + wn * 32 + ((lane & 3) << 1);
    #pragma unroll
    for (int mi = 0; mi < 4; mi++) {
        #pragma unroll
        for (int ni = 0; ni < 4; ni++) {
            const int r = erow + mi * 16;
            const int c = ecol + ni * 8;
            float2 add = make_float2(0.f, 0.f);
            if (bias) {
                float2 bb = *reinterpret_cast<const float2*>(bias + c);
                add.x += bb.x; add.y += bb.y;
            }
            float2 v0, v1;
            v0.x = alpha * acc[mi][ni][0] + add.x;
            v0.y = alpha * acc[mi][ni][1] + add.y;
            v1.x = alpha * acc[mi][ni][2] + add.x;
            v1.y = alpha * acc[mi][ni][3] + add.y;
            if (resid) {
                float2 r0 = *reinterpret_cast<const float2*>(resid + (size_t)r * ldc + c);
                float2 r1 = *reinterpret_cast<const float2*>(resid + (size_t)(r + 8) * ldc + c);
                v0.x += r0.x; v0.y += r0.y;
                v1.x += r1.x; v1.y += r1.y;
            }
            *reinterpret_cast<float2*>(C + (size_t)r * ldc + c)       = v0;
            *reinterpret_cast<float2*>(C + (size_t)(r + 8) * ldc + c) = v1;
        }
    }
}

// ----------------------------------------------------------------------------
// One block (256 threads, 8 warps) per (b,h,q) row of scores.
//   row max & sum(exp), per-warp barrier-free top-20 of its 256-chunk,
//   warp 0 merges 160 candidates -> global top-20 -> probs -> sparse AV.
// top_k(softmax(s)) == top_k(s).
// ----------------------------------------------------------------------------
__global__ __launch_bounds__(256)
void softmax_topk_av()
{
    const int tid  = threadIdx.x;
    const int lane = tid & 31;
    const int wid  = tid >> 5;             // 0..7
    const int row  = blockIdx.x;           // (b*H + h)*LQ + q
    const int q    = row & (NLQ - 1);
    const int bh   = row >> 9;             // LQ = 512
    const int h    = bh & (NH - 1);
    const int b    = bh >> 3;

    const float* s = g_S + (size_t)row * NLK;
    const int base = wid << 8;             // this warp's 256-element chunk

    float v[8];
    #pragma unroll
    for (int i = 0; i < 8; i++) v[i] = s[base + lane + (i << 5)];   // coalesced

    __shared__ float smax[8];
    __shared__ float ssum[8];
    __shared__ float candV[8 * NTOPK];
    __shared__ int   candI[8 * NTOPK];
    __shared__ int   topI[NTOPK];
    __shared__ float topP[NTOPK];
    __shared__ float red[256];

    // ---- row max ----
    float m = v[0];
    #pragma unroll
    for (int i = 1; i < 8; i++) m = fmaxf(m, v[i]);
    #pragma unroll
    for (int off = 16; off > 0; off >>= 1)
        m = fmaxf(m, __shfl_xor_sync(0xffffffffu, m, off));
    if (lane == 0) smax[wid] = m;
    __syncthreads();
    float gm = smax[0];
    #pragma unroll
    for (int w = 1; w < 8; w++) gm = fmaxf(gm, smax[w]);

    // ---- row sum(exp) ----
    float ls = 0.f;
    #pragma unroll
    for (int i = 0; i < 8; i++) ls += expf(v[i] - gm);
    #pragma unroll
    for (int off = 16; off > 0; off >>= 1)
        ls += __shfl_xor_sync(0xffffffffu, ls, off);
    if (lane == 0) ssum[wid] = ls;
    __syncthreads();
    float denom = ssum[0];
    #pragma unroll
    for (int w = 1; w < 8; w++) denom += ssum[w];

    // ---- per-warp top-20 (barrier-free) ----
    #pragma unroll 1
    for (int t = 0; t < NTOPK; t++) {
        float bv = v[0];
        int   bs = 0;
        #pragma unroll
        for (int i = 1; i < 8; i++)
            if (v[i] > bv) { bv = v[i]; bs = i; }
        int bidx = base + lane + (bs << 5);
        #pragma unroll
        for (int off = 16; off > 0; off >>= 1) {
            float ov = __shfl_xor_sync(0xffffffffu, bv, off);
            int   oi = __shfl_xor_sync(0xffffffffu, bidx, off);
            if (ov > bv || (ov == bv && oi < bidx)) { bv = ov; bidx = oi; }
        }
        const int rel = bidx - base;
        if (lane == (rel & 31)) {
            const int slot = rel >> 5;
            #pragma unroll
            for (int i = 0; i < 8; i++) if (i == slot) v[i] = -FLT_MAX;
        }
        if (lane == 0) { candV[wid * NTOPK + t] = bv; candI[wid * NTOPK + t] = bidx; }
    }
    __syncthreads();

    // ---- warp 0 merges 160 candidates -> top-20 ----
    if (wid == 0) {
        float cv[5]; int ci[5];
        #pragma unroll
        for (int i = 0; i < 5; i++) { cv[i] = candV[lane + (i << 5)]; ci[i] = candI[lane + (i << 5)]; }
        #pragma unroll 1
        for (int t = 0; t < NTOPK; t++) {
            float bv = cv[0];
            int   bs = 0;
            #pragma unroll
            for (int i = 1; i < 5; i++)
                if (cv[i] > bv) { bv = cv[i]; bs = i; }
            int bidx = (bv == -FLT_MAX) ? 0x7fffffff : ci[bs];
            #pragma unroll
            for (int off = 16; off > 0; off >>= 1) {
                float ov = __shfl_xor_sync(0xffffffffu, bv, off);
                int   oi = __shfl_xor_sync(0xffffffffu, bidx, off);
                if (ov > bv || (ov == bv && oi < bidx)) { bv = ov; bidx = oi; }
            }
            #pragma unroll
            for (int i = 0; i < 5; i++) if (ci[i] == bidx) cv[i] = -FLT_MAX;
            if (lane == 0) { topI[t] = bidx; topP[t] = expf(bv - gm) / denom; }
        }
    }
    __syncthreads();

    // ---- sparse AV: out[d] = sum_j p_j * V[b, idx_j, h*64+d] ----
    const int d = tid & 63;
    const int g = tid >> 6;                // 4 groups of 5 indices each
    const float* Vb = g_V + (size_t)b * NLK * NE + h * NHD + d;
    float a = 0.f;
    #pragma unroll
    for (int j = g; j < NTOPK; j += 4)
        a = fmaf(topP[j], Vb[(size_t)topI[j] * NE], a);
    red[tid] = a;
    __syncthreads();
    if (g == 0)
        g_O[(size_t)(b * NLQ + q) * NE + h * NHD + d] =
            red[tid] + red[tid + 64] + red[tid + 128] + red[tid + 192];
}

// ----------------------------------------------------------------------------
extern "C" void kernel_launch(void* const* d_in, const int* in_sizes, int n_in,
                              void* d_out, int out_size)
{
    const float* q  = (const float*)d_in[0];
    const float* k  = (const float*)d_in[1];
    const float* v  = (const float*)d_in[2];
    const float* Wq = (const float*)d_in[3];
    const float* Wk = (const float*)d_in[4];
    const float* Wv = (const float*)d_in[5];
    const float* Wo = (const float*)d_in[6];
    const float* bo = (const float*)d_in[7];
    float* out = (float*)d_out;

    float *gQ, *gK, *gV, *gS, *gO;
    cudaGetSymbolAddress((void**)&gQ, g_Q);
    cudaGetSymbolAddress((void**)&gK, g_K);
    cudaGetSymbolAddress((void**)&gV, g_V);
    cudaGetSymbolAddress((void**)&gS, g_S);
    cudaGetSymbolAddress((void**)&gO, g_O);

    dim3 blk(256);

    // Q = q @ Wq^T : [4096,512] x [512,512]^T
    gemm_tf32<<<dim3(NE / 128, (NB * NLQ) / 128, 1), blk>>>(
        q, Wq, gQ, NE, NE, NE, NE, 1.0f,
        0, 0, 0, 0, 0, 1, nullptr, nullptr);

    // K = k @ Wk^T : [16384,512]
    gemm_tf32<<<dim3(NE / 128, (NB * NLK) / 128, 1), blk>>>(
        k, Wk, gK, NE, NE, NE, NE, 1.0f,
        0, 0, 0, 0, 0, 1, nullptr, nullptr);

    // V = v @ Wv^T : [16384,512]
    gemm_tf32<<<dim3(NE / 128, (NB * NLK) / 128, 1), blk>>>(
        v, Wv, gV, NE, NE, NE, NE, 1.0f,
        0, 0, 0, 0, 0, 1, nullptr, nullptr);

    // S[b,h] = (1/8) * Q_h @ K_h^T : per (b,h): [512,64] x [2048,64]^T
    gemm_tf32<<<dim3(NLK / 128, NLQ / 128, NB * NH), blk>>>(
        gQ, gK, gS, NHD, NE, NE, NLK, 0.125f,
        (size_t)NLQ * NE, (size_t)NHD,          // A strides (b, h)
        (size_t)NLK * NE, (size_t)NHD,          // B strides (b, h)
        (size_t)NLQ * NLK, NH,                  // C stride per z, hdiv
        nullptr, nullptr);

    // softmax + top-20 + sparse AV
    softmax_topk_av<<<NB * NH * NLQ, blk>>>();

    // out = O @ Wo^T + bo + q
    gemm_tf32<<<dim3(NE / 128, (NB * NLQ) / 128, 1), blk>>>(
        gO, Wo, out, NE, NE, NE, NE, 1.0f,
        0, 0, 0, 0, 0, 1, bo, q);
}

// round 11
// speedup vs baseline: 1.4610x; 1.0406x over previous
#include <cuda_runtime.h>
#include <cfloat>
#include <math.h>
#include <stdint.h>

#define NB    8
#define NLQ   512
#define NLK   2048
#define NE    512
#define NH    8
#define NHD   64
#define NTOPK 20

// Scratch (allocation-free rule: __device__ globals)
__device__ float g_Q[(size_t)NB * NLQ * NE];             // 8 MB
__device__ float g_K[(size_t)NB * NLK * NE];             // 32 MB
__device__ float g_V[(size_t)NB * NLK * NE];             // 32 MB
__device__ float g_S[(size_t)NB * NH * NLQ * NLK];       // 256 MB
__device__ float g_O[(size_t)NB * NLQ * NE];             // 8 MB

__device__ __forceinline__ float to_tf32(float x) {
    uint32_t u;
    asm("cvt.rna.tf32.f32 %0, %1;" : "=r"(u) : "f"(x));
    return __uint_as_float(u);
}

__device__ __forceinline__ uint32_t smem_u32(const void* p) {
    return (uint32_t)__cvta_generic_to_shared(p);
}

#define LDSM_X4(R0, R1, R2, R3, ADDR)                                          \
    asm volatile("ldmatrix.sync.aligned.m8n8.x4.shared.b16 {%0,%1,%2,%3}, [%4];" \
                 : "=r"(R0), "=r"(R1), "=r"(R2), "=r"(R3) : "r"(ADDR))

#define MMA_TF32(C, A, B0, B1)                                                  \
    asm volatile("mma.sync.aligned.m16n8k8.row.col.f32.tf32.tf32.f32 "          \
                 "{%0,%1,%2,%3}, {%4,%5,%6,%7}, {%8,%9}, {%0,%1,%2,%3};"        \
                 : "+f"((C)[0]), "+f"((C)[1]), "+f"((C)[2]), "+f"((C)[3])       \
                 : "r"((A)[0]), "r"((A)[1]), "r"((A)[2]), "r"((A)[3]),          \
                   "r"(B0), "r"(B1))

// ----------------------------------------------------------------------------
// C[m,n] = alpha * sum_k A[m,k] * Bw[n,k]   (+ optional bias[n] + resid[m,n])
// TF32 tensor-core GEMM: 128x128 block tile, BK=32, 256 threads (8 warps, 2x4),
// warp tile 64x32 via m16n8k8 atoms (4x4). k-major smem, stride 36 floats
// (conflict-free for ldmatrix: 144B row stride spreads across all banks).
// Register-prefetch pipeline over K tiles. Batched via blockIdx.z.
// ----------------------------------------------------------------------------
__global__ __launch_bounds__(256, 2)
void gemm_tf32(const float* __restrict__ A, const float* __restrict__ Bw,
               float* __restrict__ C,
               int K, int lda, int ldb, int ldc, float alpha,
               size_t sAb, size_t sAh, size_t sBb, size_t sBh, size_t sCz, int hdiv,
               const float* __restrict__ bias, const float* __restrict__ resid)
{
    __shared__ float As[128][36];
    __shared__ float Bs[128][36];

    const int tid  = threadIdx.x;
    const int lane = tid & 31;
    const int wid  = tid >> 5;
    const int wm   = wid >> 2;          // 0..1 -> 64 rows each
    const int wn   = wid & 3;           // 0..3 -> 32 cols each
    const int rowBase = blockIdx.y * 128;
    const int colBase = blockIdx.x * 128;

    const int z  = blockIdx.z;
    const int zb = z / hdiv;
    const int zh = z - zb * hdiv;
    A  += (size_t)zb * sAb + (size_t)zh * sAh;
    Bw += (size_t)zb * sBb + (size_t)zh * sBh;
    C  += (size_t)z * sCz;

    // loader coords: 4 float4 per thread per matrix (128 rows x 32 k)
    int lrow[4], lcol[4];
    #pragma unroll
    for (int i = 0; i < 4; i++) {
        int f = tid + (i << 8);
        lrow[i] = f >> 3;
        lcol[i] = (f & 7) << 2;
    }

    // fragment smem byte addresses
    const int arow = wm * 64 + (lane & 15);
    const int acol = (lane >> 4) << 2;
    uint32_t aAddr[4];
    #pragma unroll
    for (int mi = 0; mi < 4; mi++)
        aAddr[mi] = smem_u32(&As[arow + mi * 16][acol]);
    const int brow = wn * 32 + ((lane >> 4) << 3) + (lane & 7);
    const int bcol = ((lane >> 3) & 1) << 2;
    uint32_t bAddr[2];
    #pragma unroll
    for (int p = 0; p < 2; p++)
        bAddr[p] = smem_u32(&Bs[brow + p * 16][bcol]);

    float acc[4][4][4];
    #pragma unroll
    for (int mi = 0; mi < 4; mi++)
        #pragma unroll
        for (int ni = 0; ni < 4; ni++)
            #pragma unroll
            for (int r = 0; r < 4; r++) acc[mi][ni][r] = 0.f;

    float4 pa[4], pb[4];

    // prologue: load K-tile 0
    #pragma unroll
    for (int i = 0; i < 4; i++) {
        pa[i] = *reinterpret_cast<const float4*>(A  + (size_t)(rowBase + lrow[i]) * lda + lcol[i]);
        pb[i] = *reinterpret_cast<const float4*>(Bw + (size_t)(colBase + lrow[i]) * ldb + lcol[i]);
    }
    #pragma unroll
    for (int i = 0; i < 4; i++) {
        float* da = &As[lrow[i]][lcol[i]];
        da[0] = to_tf32(pa[i].x); da[1] = to_tf32(pa[i].y);
        da[2] = to_tf32(pa[i].z); da[3] = to_tf32(pa[i].w);
        float* db = &Bs[lrow[i]][lcol[i]];
        db[0] = to_tf32(pb[i].x); db[1] = to_tf32(pb[i].y);
        db[2] = to_tf32(pb[i].z); db[3] = to_tf32(pb[i].w);
    }
    __syncthreads();

    for (int k0 = 0; k0 < K; k0 += 32) {
        const bool has = (k0 + 32) < K;
        if (has) {
            #pragma unroll
            for (int i = 0; i < 4; i++) {
                pa[i] = *reinterpret_cast<const float4*>(A  + (size_t)(rowBase + lrow[i]) * lda + k0 + 32 + lcol[i]);
                pb[i] = *reinterpret_cast<const float4*>(Bw + (size_t)(colBase + lrow[i]) * ldb + k0 + 32 + lcol[i]);
            }
        }

        #pragma unroll
        for (int ks = 0; ks < 4; ks++) {
            const uint32_t koff = ks * 32;        // 8 floats = 32 bytes
            uint32_t a[4][4], b[2][4];
            #pragma unroll
            for (int mi = 0; mi < 4; mi++)
                LDSM_X4(a[mi][0], a[mi][1], a[mi][2], a[mi][3], aAddr[mi] + koff);
            #pragma unroll
            for (int p = 0; p < 2; p++)
                LDSM_X4(b[p][0], b[p][1], b[p][2], b[p][3], bAddr[p] + koff);
            #pragma unroll
            for (int mi = 0; mi < 4; mi++)
                #pragma unroll
                for (int ni = 0; ni < 4; ni++) {
                    const int p = ni >> 1, o = (ni & 1) << 1;
                    MMA_TF32(acc[mi][ni], a[mi], b[p][o], b[p][o + 1]);
                }
        }
        __syncthreads();

        if (has) {
            #pragma unroll
            for (int i = 0; i < 4; i++) {
                float* da = &As[lrow[i]][lcol[i]];
                da[0] = to_tf32(pa[i].x); da[1] = to_tf32(pa[i].y);
                da[2] = to_tf32(pa[i].z); da[3] = to_tf32(pa[i].w);
                float* db = &Bs[lrow[i]][lcol[i]];
                db[0] = to_tf32(pb[i].x); db[1] = to_tf32(pb[i].y);
                db[2] = to_tf32(pb[i].z); db[3] = to_tf32(pb[i].w);
            }
            __syncthreads();
        }
    }

    // epilogue: c0 (r, c), c1 (r, c+1), c2 (r+8, c), c3 (r+8, c+1)
    const int erow = rowBase + wm * 64 + (lane >> 2);
    const int ecol = colBase + wn * 32 + ((lane & 3) << 1);
    #pragma unroll
    for (int mi = 0; mi < 4; mi++) {
        #pragma unroll
        for (int ni = 0; ni < 4; ni++) {
            const int r = erow + mi * 16;
            const int c = ecol + ni * 8;
            float2 add = make_float2(0.f, 0.f);
            if (bias) {
                float2 bb = *reinterpret_cast<const float2*>(bias + c);
                add.x += bb.x; add.y += bb.y;
            }
            float2 v0, v1;
            v0.x = alpha * acc[mi][ni][0] + add.x;
            v0.y = alpha * acc[mi][ni][1] + add.y;
            v1.x = alpha * acc[mi][ni][2] + add.x;
            v1.y = alpha * acc[mi][ni][3] + add.y;
            if (resid) {
                float2 r0 = *reinterpret_cast<const float2*>(resid + (size_t)r * ldc + c);
                float2 r1 = *reinterpret_cast<const float2*>(resid + (size_t)(r + 8) * ldc + c);
                v0.x += r0.x; v0.y += r0.y;
                v1.x += r1.x; v1.y += r1.y;
            }
            *reinterpret_cast<float2*>(C + (size_t)r * ldc + c)       = v0;
            *reinterpret_cast<float2*>(C + (size_t)(r + 8) * ldc + c) = v1;
        }
    }
}

// ----------------------------------------------------------------------------
// One block (256 threads, 8 warps) per (b,h,q) row of scores.
//   row max & sum(exp), per-warp barrier-free top-20 of its 256-chunk,
//   warp 0 merges 160 candidates -> global top-20 -> probs -> sparse AV.
// top_k(softmax(s)) == top_k(s).
// ----------------------------------------------------------------------------
__global__ __launch_bounds__(256)
void softmax_topk_av()
{
    const int tid  = threadIdx.x;
    const int lane = tid & 31;
    const int wid  = tid >> 5;             // 0..7
    const int row  = blockIdx.x;           // (b*H + h)*LQ + q
    const int q    = row & (NLQ - 1);
    const int bh   = row >> 9;             // LQ = 512
    const int h    = bh & (NH - 1);
    const int b    = bh >> 3;

    const float* s = g_S + (size_t)row * NLK;
    const int base = wid << 8;             // this warp's 256-element chunk

    float v[8];
    #pragma unroll
    for (int i = 0; i < 8; i++) v[i] = s[base + lane + (i << 5)];   // coalesced

    __shared__ float smax[8];
    __shared__ float ssum[8];
    __shared__ float candV[8 * NTOPK];
    __shared__ int   candI[8 * NTOPK];
    __shared__ int   topI[NTOPK];
    __shared__ float topP[NTOPK];
    __shared__ float red[256];

    // ---- row max ----
    float m = v[0];
    #pragma unroll
    for (int i = 1; i < 8; i++) m = fmaxf(m, v[i]);
    #pragma unroll
    for (int off = 16; off > 0; off >>= 1)
        m = fmaxf(m, __shfl_xor_sync(0xffffffffu, m, off));
    if (lane == 0) smax[wid] = m;
    __syncthreads();
    float gm = smax[0];
    #pragma unroll
    for (int w = 1; w < 8; w++) gm = fmaxf(gm, smax[w]);

    // ---- row sum(exp) ----
    float ls = 0.f;
    #pragma unroll
    for (int i = 0; i < 8; i++) ls += expf(v[i] - gm);
    #pragma unroll
    for (int off = 16; off > 0; off >>= 1)
        ls += __shfl_xor_sync(0xffffffffu, ls, off);
    if (lane == 0) ssum[wid] = ls;
    __syncthreads();
    float denom = ssum[0];
    #pragma unroll
    for (int w = 1; w < 8; w++) denom += ssum[w];

    // ---- per-warp top-20 (barrier-free) ----
    #pragma unroll 1
    for (int t = 0; t < NTOPK; t++) {
        float bv = v[0];
        int   bs = 0;
        #pragma unroll
        for (int i = 1; i < 8; i++)
            if (v[i] > bv) { bv = v[i]; bs = i; }
        int bidx = base + lane + (bs << 5);
        #pragma unroll
        for (int off = 16; off > 0; off >>= 1) {
            float ov = __shfl_xor_sync(0xffffffffu, bv, off);
            int   oi = __shfl_xor_sync(0xffffffffu, bidx, off);
            if (ov > bv || (ov == bv && oi < bidx)) { bv = ov; bidx = oi; }
        }
        const int rel = bidx - base;
        if (lane == (rel & 31)) {
            const int slot = rel >> 5;
            #pragma unroll
            for (int i = 0; i < 8; i++) if (i == slot) v[i] = -FLT_MAX;
        }
        if (lane == 0) { candV[wid * NTOPK + t] = bv; candI[wid * NTOPK + t] = bidx; }
    }
    __syncthreads();

    // ---- warp 0 merges 160 candidates -> top-20 ----
    if (wid == 0) {
        float cv[5]; int ci[5];
        #pragma unroll
        for (int i = 0; i < 5; i++) { cv[i] = candV[lane + (i << 5)]; ci[i] = candI[lane + (i << 5)]; }
        #pragma unroll 1
        for (int t = 0; t < NTOPK; t++) {
            float bv = cv[0];
            int   bs = 0;
            #pragma unroll
            for (int i = 1; i < 5; i++)
                if (cv[i] > bv) { bv = cv[i]; bs = i; }
            int bidx = (bv == -FLT_MAX) ? 0x7fffffff : ci[bs];
            #pragma unroll
            for (int off = 16; off > 0; off >>= 1) {
                float ov = __shfl_xor_sync(0xffffffffu, bv, off);
                int   oi = __shfl_xor_sync(0xffffffffu, bidx, off);
                if (ov > bv || (ov == bv && oi < bidx)) { bv = ov; bidx = oi; }
            }
            #pragma unroll
            for (int i = 0; i < 5; i++) if (ci[i] == bidx) cv[i] = -FLT_MAX;
            if (lane == 0) { topI[t] = bidx; topP[t] = expf(bv - gm) / denom; }
        }
    }
    __syncthreads();

    // ---- sparse AV: out[d] = sum_j p_j * V[b, idx_j, h*64+d] ----
    const int d = tid & 63;
    const int g = tid >> 6;                // 4 groups of 5 indices each
    const float* Vb = g_V + (size_t)b * NLK * NE + h * NHD + d;
    float a = 0.f;
    #pragma unroll
    for (int j = g; j < NTOPK; j += 4)
        a = fmaf(topP[j], Vb[(size_t)topI[j] * NE], a);
    red[tid] = a;
    __syncthreads();
    if (g == 0)
        g_O[(size_t)(b * NLQ + q) * NE + h * NHD + d] =
            red[tid] + red[tid + 64] + red[tid + 128] + red[tid + 192];
}

// ----------------------------------------------------------------------------
extern "C" void kernel_launch(void* const* d_in, const int* in_sizes, int n_in,
                              void* d_out, int out_size)
{
    const float* q  = (const float*)d_in[0];
    const float* k  = (const float*)d_in[1];
    const float* v  = (const float*)d_in[2];
    const float* Wq = (const float*)d_in[3];
    const float* Wk = (const float*)d_in[4];
    const float* Wv = (const float*)d_in[5];
    const float* Wo = (const float*)d_in[6];
    const float* bo = (const float*)d_in[7];
    float* out = (float*)d_out;

    float *gQ, *gK, *gV, *gS, *gO;
    cudaGetSymbolAddress((void**)&gQ, g_Q);
    cudaGetSymbolAddress((void**)&gK, g_K);
    cudaGetSymbolAddress((void**)&gV, g_V);
    cudaGetSymbolAddress((void**)&gS, g_S);
    cudaGetSymbolAddress((void**)&gO, g_O);

    dim3 blk(256);

    // Q = q @ Wq^T : [4096,512] x [512,512]^T
    gemm_tf32<<<dim3(NE / 128, (NB * NLQ) / 128, 1), blk>>>(
        q, Wq, gQ, NE, NE, NE, NE, 1.0f,
        0, 0, 0, 0, 0, 1, nullptr, nullptr);

    // K = k @ Wk^T : [16384,512]
    gemm_tf32<<<dim3(NE / 128, (NB * NLK) / 128, 1), blk>>>(
        k, Wk, gK, NE, NE, NE, NE, 1.0f,
        0, 0, 0, 0, 0, 1, nullptr, nullptr);

    // V = v @ Wv^T : [16384,512]
    gemm_tf32<<<dim3(NE / 128, (NB * NLK) / 128, 1), blk>>>(
        v, Wv, gV, NE, NE, NE, NE, 1.0f,
        0, 0, 0, 0, 0, 1, nullptr, nullptr);

    // S[b,h] = (1/8) * Q_h @ K_h^T : per (b,h): [512,64] x [2048,64]^T
    gemm_tf32<<<dim3(NLK / 128, NLQ / 128, NB * NH), blk>>>(
        gQ, gK, gS, NHD, NE, NE, NLK, 0.125f,
        (size_t)NLQ * NE, (size_t)NHD,          // A strides (b, h)
        (size_t)NLK * NE, (size_t)NHD,          // B strides (b, h)
        (size_t)NLQ * NLK, NH,                  // C stride per z, hdiv
        nullptr, nullptr);

    // softmax + top-20 + sparse AV
    softmax_topk_av<<<NB * NH * NLQ, blk>>>();

    // out = O @ Wo^T + bo + q
    gemm_tf32<<<dim3(NE / 128, (NB * NLQ) / 128, 1), blk>>>(
        gO, Wo, out, NE, NE, NE, NE, 1.0f,
        0, 0, 0, 0, 0, 1, bo, q);
}

// round 12
// speedup vs baseline: 1.4924x; 1.0215x over previous
#include <cuda_runtime.h>
#include <cfloat>
#include <math.h>
#include <stdint.h>

#define NB    8
#define NLQ   512
#define NLK   2048
#define NE    512
#define NH    8
#define NHD   64
#define NTOPK 20
#define FULL  0xffffffffu

// Scratch (allocation-free rule: __device__ globals)
__device__ float g_Q[(size_t)NB * NLQ * NE];             // 8 MB
__device__ float g_K[(size_t)NB * NLK * NE];             // 32 MB
__device__ float g_V[(size_t)NB * NLK * NE];             // 32 MB
__device__ float g_O[(size_t)NB * NLQ * NE];             // 8 MB

__device__ __forceinline__ float to_tf32(float x) {
    uint32_t u;
    asm("cvt.rna.tf32.f32 %0, %1;" : "=r"(u) : "f"(x));
    return __uint_as_float(u);
}

__device__ __forceinline__ uint32_t smem_u32(const void* p) {
    return (uint32_t)__cvta_generic_to_shared(p);
}

#define LDSM_X4(R0, R1, R2, R3, ADDR)                                          \
    asm volatile("ldmatrix.sync.aligned.m8n8.x4.shared.b16 {%0,%1,%2,%3}, [%4];" \
                 : "=r"(R0), "=r"(R1), "=r"(R2), "=r"(R3) : "r"(ADDR))

#define MMA_TF32(C, A, B0, B1)                                                  \
    asm volatile("mma.sync.aligned.m16n8k8.row.col.f32.tf32.tf32.f32 "          \
                 "{%0,%1,%2,%3}, {%4,%5,%6,%7}, {%8,%9}, {%0,%1,%2,%3};"        \
                 : "+f"((C)[0]), "+f"((C)[1]), "+f"((C)[2]), "+f"((C)[3])       \
                 : "r"((A)[0]), "r"((A)[1]), "r"((A)[2]), "r"((A)[3]),          \
                   "r"(B0), "r"(B1))

// ----------------------------------------------------------------------------
// TF32 GEMM for projections: C = A @ Bw^T (+bias +resid). 128x128 tile, BK=32.
// ----------------------------------------------------------------------------
__global__ __launch_bounds__(256, 2)
void gemm_tf32(const float* __restrict__ A, const float* __restrict__ Bw,
               float* __restrict__ C, int K, int lda, int ldb, int ldc,
               const float* __restrict__ bias, const float* __restrict__ resid)
{
    __shared__ float As[128][36];
    __shared__ float Bs[128][36];

    const int tid  = threadIdx.x;
    const int lane = tid & 31;
    const int wid  = tid >> 5;
    const int wm   = wid >> 2;
    const int wn   = wid & 3;
    const int rowBase = blockIdx.y * 128;
    const int colBase = blockIdx.x * 128;

    int lrow[4], lcol[4];
    #pragma unroll
    for (int i = 0; i < 4; i++) {
        int f = tid + (i << 8);
        lrow[i] = f >> 3;
        lcol[i] = (f & 7) << 2;
    }

    const int arow = wm * 64 + (lane & 15);
    const int acol = (lane >> 4) << 2;
    uint32_t aAddr[4];
    #pragma unroll
    for (int mi = 0; mi < 4; mi++)
        aAddr[mi] = smem_u32(&As[arow + mi * 16][acol]);
    const int brow = wn * 32 + ((lane >> 4) << 3) + (lane & 7);
    const int bcol = ((lane >> 3) & 1) << 2;
    uint32_t bAddr[2];
    #pragma unroll
    for (int p = 0; p < 2; p++)
        bAddr[p] = smem_u32(&Bs[brow + p * 16][bcol]);

    float acc[4][4][4];
    #pragma unroll
    for (int mi = 0; mi < 4; mi++)
        #pragma unroll
        for (int ni = 0; ni < 4; ni++)
            #pragma unroll
            for (int r = 0; r < 4; r++) acc[mi][ni][r] = 0.f;

    float4 pa[4], pb[4];
    #pragma unroll
    for (int i = 0; i < 4; i++) {
        pa[i] = *reinterpret_cast<const float4*>(A  + (size_t)(rowBase + lrow[i]) * lda + lcol[i]);
        pb[i] = *reinterpret_cast<const float4*>(Bw + (size_t)(colBase + lrow[i]) * ldb + lcol[i]);
    }
    #pragma unroll
    for (int i = 0; i < 4; i++) {
        float* da = &As[lrow[i]][lcol[i]];
        da[0] = to_tf32(pa[i].x); da[1] = to_tf32(pa[i].y);
        da[2] = to_tf32(pa[i].z); da[3] = to_tf32(pa[i].w);
        float* db = &Bs[lrow[i]][lcol[i]];
        db[0] = to_tf32(pb[i].x); db[1] = to_tf32(pb[i].y);
        db[2] = to_tf32(pb[i].z); db[3] = to_tf32(pb[i].w);
    }
    __syncthreads();

    for (int k0 = 0; k0 < K; k0 += 32) {
        const bool has = (k0 + 32) < K;
        if (has) {
            #pragma unroll
            for (int i = 0; i < 4; i++) {
                pa[i] = *reinterpret_cast<const float4*>(A  + (size_t)(rowBase + lrow[i]) * lda + k0 + 32 + lcol[i]);
                pb[i] = *reinterpret_cast<const float4*>(Bw + (size_t)(colBase + lrow[i]) * ldb + k0 + 32 + lcol[i]);
            }
        }
        #pragma unroll
        for (int ks = 0; ks < 4; ks++) {
            const uint32_t koff = ks * 32;
            uint32_t a[4][4], b[2][4];
            #pragma unroll
            for (int mi = 0; mi < 4; mi++)
                LDSM_X4(a[mi][0], a[mi][1], a[mi][2], a[mi][3], aAddr[mi] + koff);
            #pragma unroll
            for (int p = 0; p < 2; p++)
                LDSM_X4(b[p][0], b[p][1], b[p][2], b[p][3], bAddr[p] + koff);
            #pragma unroll
            for (int mi = 0; mi < 4; mi++)
                #pragma unroll
                for (int ni = 0; ni < 4; ni++) {
                    const int p = ni >> 1, o = (ni & 1) << 1;
                    MMA_TF32(acc[mi][ni], a[mi], b[p][o], b[p][o + 1]);
                }
        }
        __syncthreads();
        if (has) {
            #pragma unroll
            for (int i = 0; i < 4; i++) {
                float* da = &As[lrow[i]][lcol[i]];
                da[0] = to_tf32(pa[i].x); da[1] = to_tf32(pa[i].y);
                da[2] = to_tf32(pa[i].z); da[3] = to_tf32(pa[i].w);
                float* db = &Bs[lrow[i]][lcol[i]];
                db[0] = to_tf32(pb[i].x); db[1] = to_tf32(pb[i].y);
                db[2] = to_tf32(pb[i].z); db[3] = to_tf32(pb[i].w);
            }
            __syncthreads();
        }
    }

    const int erow = rowBase + wm * 64 + (lane >> 2);
    const int ecol = colBase + wn * 32 + ((lane & 3) << 1);
    #pragma unroll
    for (int mi = 0; mi < 4; mi++) {
        #pragma unroll
        for (int ni = 0; ni < 4; ni++) {
            const int r = erow + mi * 16;
            const int c = ecol + ni * 8;
            float2 add = make_float2(0.f, 0.f);
            if (bias) {
                float2 bb = *reinterpret_cast<const float2*>(bias + c);
                add.x += bb.x; add.y += bb.y;
            }
            float2 v0, v1;
            v0.x = acc[mi][ni][0] + add.x;
            v0.y = acc[mi][ni][1] + add.y;
            v1.x = acc[mi][ni][2] + add.x;
            v1.y = acc[mi][ni][3] + add.y;
            if (resid) {
                float2 r0 = *reinterpret_cast<const float2*>(resid + (size_t)r * ldc + c);
                float2 r1 = *reinterpret_cast<const float2*>(resid + (size_t)(r + 8) * ldc + c);
                v0.x += r0.x; v0.y += r0.y;
                v1.x += r1.x; v1.y += r1.y;
            }
            *reinterpret_cast<float2*>(C + (size_t)r * ldc + c)       = v0;
            *reinterpret_cast<float2*>(C + (size_t)(r + 8) * ldc + c) = v1;
        }
    }
}

// ----------------------------------------------------------------------------
// Fused attention: per block = 128 q-rows of one (b,h).
// Streams 16 K-chunks of 128 keys: TF32 MMA -> scores in smem -> online
// max/sum + exact streaming top-20 (sorted list across lanes 0..19) -> AV.
// S is never materialized in global memory.
// ----------------------------------------------------------------------------
#define QS_ST 68
#define KS_ST 68
#define SS_ST 132
// float offsets into dynamic smem
#define OFF_QS 0
#define OFF_KS (128 * QS_ST)                       // 2 buffers
#define OFF_SS (OFF_KS + 2 * 128 * KS_ST)
#define OFF_LV (OFF_SS + 128 * SS_ST)
#define OFF_LI (OFF_LV + 128 * NTOPK)
#define OFF_MS (OFF_LI + 128 * NTOPK)
#define OFF_LS (OFF_MS + 128)
#define SMEM_FLOATS (OFF_LS + 128)
#define SMEM_BYTES (SMEM_FLOATS * 4)

__global__ __launch_bounds__(256, 1)
void fused_attn()
{
    extern __shared__ float sm[];
    float (*Qs)[QS_ST] = reinterpret_cast<float(*)[QS_ST]>(sm + OFF_QS);
    float (*Ss)[SS_ST] = reinterpret_cast<float(*)[SS_ST]>(sm + OFF_SS);
    float* Lv = sm + OFF_LV;
    int*   Li = reinterpret_cast<int*>(sm + OFF_LI);
    float* Ms = sm + OFF_MS;
    float* Ls = sm + OFF_LS;

    const int tid  = threadIdx.x;
    const int lane = tid & 31;
    const int wid  = tid >> 5;
    const int q0   = blockIdx.x * 128;
    const int bh   = blockIdx.y;
    const int b    = bh >> 3;
    const int h    = bh & 7;

    const float* Qg = g_Q + (size_t)b * NLQ * NE + h * NHD;
    const float* Kg = g_K + (size_t)b * NLK * NE + h * NHD;
    const float* Vg = g_V + (size_t)b * NLK * NE + h * NHD;

    // ---- load Q tile once (scale 1/8 folded in: exact power-of-2) ----
    #pragma unroll
    for (int i = 0; i < 8; i++) {
        int f = tid + (i << 8);
        int r = f >> 4, c4 = (f & 15) << 2;
        float4 t = *reinterpret_cast<const float4*>(Qg + (size_t)(q0 + r) * NE + c4);
        float* d = &Qs[r][c4];
        d[0] = to_tf32(0.125f * t.x); d[1] = to_tf32(0.125f * t.y);
        d[2] = to_tf32(0.125f * t.z); d[3] = to_tf32(0.125f * t.w);
    }
    // ---- init state ----
    for (int idx = tid; idx < 128 * NTOPK; idx += 256) {
        Lv[idx] = -FLT_MAX;
        Li[idx] = 0x7fffffff;
    }
    if (tid < 128) { Ms[tid] = -FLT_MAX; Ls[tid] = 0.f; }

    // ---- prologue: K chunk 0 -> buffer 0 ----
    float4 kp[8];
    #pragma unroll
    for (int i = 0; i < 8; i++) {
        int f = tid + (i << 8);
        int r = f >> 4, c4 = (f & 15) << 2;
        kp[i] = *reinterpret_cast<const float4*>(Kg + (size_t)r * NE + c4);
    }
    {
        float (*Kb)[KS_ST] = reinterpret_cast<float(*)[KS_ST]>(sm + OFF_KS);
        #pragma unroll
        for (int i = 0; i < 8; i++) {
            int f = tid + (i << 8);
            int r = f >> 4, c4 = (f & 15) << 2;
            float* d = &Kb[r][c4];
            d[0] = to_tf32(kp[i].x); d[1] = to_tf32(kp[i].y);
            d[2] = to_tf32(kp[i].z); d[3] = to_tf32(kp[i].w);
        }
    }
    __syncthreads();

    // ---- MMA fragment addresses ----
    const int wm = wid >> 2, wn = wid & 3;
    const int arow = wm * 64 + (lane & 15);
    const int acol = (lane >> 4) << 2;
    uint32_t aAddr[4];
    #pragma unroll
    for (int mi = 0; mi < 4; mi++)
        aAddr[mi] = smem_u32(&Qs[arow + mi * 16][acol]);
    const int brow = wn * 32 + ((lane >> 4) << 3) + (lane & 7);
    const int bcol = ((lane >> 3) & 1) << 2;
    uint32_t bAddr[2][2];
    #pragma unroll
    for (int buf = 0; buf < 2; buf++) {
        float (*Kb)[KS_ST] = reinterpret_cast<float(*)[KS_ST]>(sm + OFF_KS + buf * 128 * KS_ST);
        #pragma unroll
        for (int p = 0; p < 2; p++)
            bAddr[buf][p] = smem_u32(&Kb[brow + p * 16][bcol]);
    }

    for (int c = 0; c < 16; c++) {
        // ---- MMA: 128x128 scores of chunk c ----
        float acc[4][4][4];
        #pragma unroll
        for (int mi = 0; mi < 4; mi++)
            #pragma unroll
            for (int ni = 0; ni < 4; ni++)
                #pragma unroll
                for (int r = 0; r < 4; r++) acc[mi][ni][r] = 0.f;

        const int buf = c & 1;
        #pragma unroll
        for (int ks = 0; ks < 8; ks++) {
            const uint32_t koff = ks * 32;
            uint32_t a[4][4], bf[2][4];
            #pragma unroll
            for (int mi = 0; mi < 4; mi++)
                LDSM_X4(a[mi][0], a[mi][1], a[mi][2], a[mi][3], aAddr[mi] + koff);
            #pragma unroll
            for (int p = 0; p < 2; p++)
                LDSM_X4(bf[p][0], bf[p][1], bf[p][2], bf[p][3], bAddr[buf][p] + koff);
            #pragma unroll
            for (int mi = 0; mi < 4; mi++)
                #pragma unroll
                for (int ni = 0; ni < 4; ni++) {
                    const int p = ni >> 1, o = (ni & 1) << 1;
                    MMA_TF32(acc[mi][ni], a[mi], bf[p][o], bf[p][o + 1]);
                }
        }

        // ---- prefetch K chunk c+1 ----
        const bool has = (c < 15);
        if (has) {
            #pragma unroll
            for (int i = 0; i < 8; i++) {
                int f = tid + (i << 8);
                int r = f >> 4, c4 = (f & 15) << 2;
                kp[i] = *reinterpret_cast<const float4*>(Kg + (size_t)((c + 1) * 128 + r) * NE + c4);
            }
        }
        __syncthreads();   // (1) prior selection done: Ss free; Ks[buf^1] free

        // ---- store scores to smem ----
        const int erow = wm * 64 + (lane >> 2);
        const int ecol = wn * 32 + ((lane & 3) << 1);
        #pragma unroll
        for (int mi = 0; mi < 4; mi++) {
            #pragma unroll
            for (int ni = 0; ni < 4; ni++) {
                const int r = erow + mi * 16;
                const int cc = ecol + ni * 8;
                Ss[r][cc]         = acc[mi][ni][0];
                Ss[r][cc + 1]     = acc[mi][ni][1];
                Ss[r + 8][cc]     = acc[mi][ni][2];
                Ss[r + 8][cc + 1] = acc[mi][ni][3];
            }
        }
        if (has) {
            float (*Kb)[KS_ST] = reinterpret_cast<float(*)[KS_ST]>(sm + OFF_KS + (buf ^ 1) * 128 * KS_ST);
            #pragma unroll
            for (int i = 0; i < 8; i++) {
                int f = tid + (i << 8);
                int r = f >> 4, c4 = (f & 15) << 2;
                float* d = &Kb[r][c4];
                d[0] = to_tf32(kp[i].x); d[1] = to_tf32(kp[i].y);
                d[2] = to_tf32(kp[i].z); d[3] = to_tf32(kp[i].w);
            }
        }
        __syncthreads();   // (2) Ss + next K buffer ready

        // ---- selection: each warp owns rows [wid*16, wid*16+16) ----
        const int k0 = c << 7;
        for (int rr = 0; rr < 16; rr++) {
            const int r = (wid << 4) + rr;
            float lv = (lane < NTOPK) ? Lv[r * NTOPK + lane] : -FLT_MAX;
            int   li = (lane < NTOPK) ? Li[r * NTOPK + lane] : 0x7fffffff;
            float minV = __shfl_sync(FULL, lv, NTOPK - 1);

            float v[4];
            #pragma unroll
            for (int i = 0; i < 4; i++) v[i] = Ss[r][lane + (i << 5)];

            // online max / sum(exp)
            float mc = fmaxf(fmaxf(v[0], v[1]), fmaxf(v[2], v[3]));
            #pragma unroll
            for (int off = 16; off > 0; off >>= 1)
                mc = fmaxf(mc, __shfl_xor_sync(FULL, mc, off));
            const float m_old = Ms[r];
            const float m_new = fmaxf(m_old, mc);
            float e = expf(v[0] - m_new) + expf(v[1] - m_new)
                    + expf(v[2] - m_new) + expf(v[3] - m_new);
            #pragma unroll
            for (int off = 16; off > 0; off >>= 1)
                e += __shfl_xor_sync(FULL, e, off);
            if (lane == 0) {
                Ms[r] = m_new;
                Ls[r] = Ls[r] * expf(m_old - m_new) + e;
            }

            // streaming insert into sorted top-20 (val desc, idx asc)
            #pragma unroll
            for (int i = 0; i < 4; i++) {
                float cv   = v[i];
                int   cidx = k0 + lane + (i << 5);
                while (true) {
                    unsigned mask = __ballot_sync(FULL, cv > minV);
                    if (!mask) break;
                    const int src = __ffs(mask) - 1;
                    const float bv = __shfl_sync(FULL, cv, src);
                    const int   bi = __shfl_sync(FULL, cidx, src);
                    unsigned gt = __ballot_sync(FULL,
                        (lane < NTOPK) && (lv > bv || (lv == bv && li < bi)));
                    const int pos = __popc(gt);
                    const float upv = __shfl_up_sync(FULL, lv, 1);
                    const int   upi = __shfl_up_sync(FULL, li, 1);
                    if (lane < NTOPK) {
                        if (lane == pos)      { lv = bv;  li = bi;  }
                        else if (lane > pos)  { lv = upv; li = upi; }
                    }
                    minV = __shfl_sync(FULL, lv, NTOPK - 1);
                    if (lane == src) cv = -FLT_MAX;
                }
            }
            if (lane < NTOPK) {
                Lv[r * NTOPK + lane] = lv;
                Li[r * NTOPK + lane] = li;
            }
        }
    }
    __syncthreads();

    // ---- epilogue: probs + sparse AV ----
    for (int rr = 0; rr < 16; rr++) {
        const int r = (wid << 4) + rr;
        const float gm = Ms[r];
        const float denom = Ls[r];
        float lv = (lane < NTOPK) ? Lv[r * NTOPK + lane] : 0.f;
        int   li = (lane < NTOPK) ? Li[r * NTOPK + lane] : 0;
        const float p = (lane < NTOPK) ? expf(lv - gm) / denom : 0.f;
        float a0 = 0.f, a1 = 0.f;
        #pragma unroll
        for (int j = 0; j < NTOPK; j++) {
            const float pj = __shfl_sync(FULL, p, j);
            const int   ij = __shfl_sync(FULL, li, j);
            const float* vp = Vg + (size_t)ij * NE;
            a0 = fmaf(pj, vp[lane], a0);
            a1 = fmaf(pj, vp[lane + 32], a1);
        }
        float* op = g_O + (size_t)(b * NLQ + q0 + r) * NE + h * NHD;
        op[lane]      = a0;
        op[lane + 32] = a1;
    }
}

// ----------------------------------------------------------------------------
extern "C" void kernel_launch(void* const* d_in, const int* in_sizes, int n_in,
                              void* d_out, int out_size)
{
    const float* q  = (const float*)d_in[0];
    const float* k  = (const float*)d_in[1];
    const float* v  = (const float*)d_in[2];
    const float* Wq = (const float*)d_in[3];
    const float* Wk = (const float*)d_in[4];
    const float* Wv = (const float*)d_in[5];
    const float* Wo = (const float*)d_in[6];
    const float* bo = (const float*)d_in[7];
    float* out = (float*)d_out;

    float *gQ, *gK, *gV, *gO;
    cudaGetSymbolAddress((void**)&gQ, g_Q);
    cudaGetSymbolAddress((void**)&gK, g_K);
    cudaGetSymbolAddress((void**)&gV, g_V);
    cudaGetSymbolAddress((void**)&gO, g_O);

    cudaFuncSetAttribute(fused_attn, cudaFuncAttributeMaxDynamicSharedMemorySize,
                         SMEM_BYTES);

    dim3 blk(256);

    // Q = q @ Wq^T
    gemm_tf32<<<dim3(NE / 128, (NB * NLQ) / 128), blk>>>(
        q, Wq, gQ, NE, NE, NE, NE, nullptr, nullptr);

    // K = k @ Wk^T
    gemm_tf32<<<dim3(NE / 128, (NB * NLK) / 128), blk>>>(
        k, Wk, gK, NE, NE, NE, NE, nullptr, nullptr);

    // V = v @ Wv^T
    gemm_tf32<<<dim3(NE / 128, (NB * NLK) / 128), blk>>>(
        v, Wv, gV, NE, NE, NE, NE, nullptr, nullptr);

    // fused scores + softmax + top-20 + AV
    fused_attn<<<dim3(NLQ / 128, NB * NH), blk, SMEM_BYTES>>>();

    // out = O @ Wo^T + bo + q
    gemm_tf32<<<dim3(NE / 128, (NB * NLQ) / 128), blk>>>(
        gO, Wo, out, NE, NE, NE, NE, bo, q);
}

// round 13
// speedup vs baseline: 1.4960x; 1.0024x over previous
#include <cuda_runtime.h>
#include <cfloat>
#include <math.h>
#include <stdint.h>

#define NB    8
#define NLQ   512
#define NLK   2048
#define NE    512
#define NH    8
#define NHD   64
#define NTOPK 20
#define FULL  0xffffffffu

// Scratch (allocation-free rule: __device__ globals)
__device__ float g_Q[(size_t)NB * NLQ * NE];             // 8 MB
__device__ float g_K[(size_t)NB * NLK * NE];             // 32 MB
__device__ float g_V[(size_t)NB * NLK * NE];             // 32 MB
__device__ float g_O[(size_t)NB * NLQ * NE];             // 8 MB

__device__ __forceinline__ float to_tf32(float x) {
    uint32_t u;
    asm("cvt.rna.tf32.f32 %0, %1;" : "=r"(u) : "f"(x));
    return __uint_as_float(u);
}

__device__ __forceinline__ uint32_t smem_u32(const void* p) {
    return (uint32_t)__cvta_generic_to_shared(p);
}

#define LDSM_X4(R0, R1, R2, R3, ADDR)                                          \
    asm volatile("ldmatrix.sync.aligned.m8n8.x4.shared.b16 {%0,%1,%2,%3}, [%4];" \
                 : "=r"(R0), "=r"(R1), "=r"(R2), "=r"(R3) : "r"(ADDR))

#define MMA_TF32(C, A, B0, B1)                                                  \
    asm volatile("mma.sync.aligned.m16n8k8.row.col.f32.tf32.tf32.f32 "          \
                 "{%0,%1,%2,%3}, {%4,%5,%6,%7}, {%8,%9}, {%0,%1,%2,%3};"        \
                 : "+f"((C)[0]), "+f"((C)[1]), "+f"((C)[2]), "+f"((C)[3])       \
                 : "r"((A)[0]), "r"((A)[1]), "r"((A)[2]), "r"((A)[3]),          \
                   "r"(B0), "r"(B1))

// ----------------------------------------------------------------------------
// TF32 GEMM for projections: C = A @ Bw^T (+bias +resid). 128x128 tile, BK=32.
// ----------------------------------------------------------------------------
__global__ __launch_bounds__(256, 2)
void gemm_tf32(const float* __restrict__ A, const float* __restrict__ Bw,
               float* __restrict__ C, int K, int lda, int ldb, int ldc,
               const float* __restrict__ bias, const float* __restrict__ resid)
{
    __shared__ float As[128][36];
    __shared__ float Bs[128][36];

    const int tid  = threadIdx.x;
    const int lane = tid & 31;
    const int wid  = tid >> 5;
    const int wm   = wid >> 2;
    const int wn   = wid & 3;
    const int rowBase = blockIdx.y * 128;
    const int colBase = blockIdx.x * 128;

    int lrow[4], lcol[4];
    #pragma unroll
    for (int i = 0; i < 4; i++) {
        int f = tid + (i << 8);
        lrow[i] = f >> 3;
        lcol[i] = (f & 7) << 2;
    }

    const int arow = wm * 64 + (lane & 15);
    const int acol = (lane >> 4) << 2;
    uint32_t aAddr[4];
    #pragma unroll
    for (int mi = 0; mi < 4; mi++)
        aAddr[mi] = smem_u32(&As[arow + mi * 16][acol]);
    const int brow = wn * 32 + ((lane >> 4) << 3) + (lane & 7);
    const int bcol = ((lane >> 3) & 1) << 2;
    uint32_t bAddr[2];
    #pragma unroll
    for (int p = 0; p < 2; p++)
        bAddr[p] = smem_u32(&Bs[brow + p * 16][bcol]);

    float acc[4][4][4];
    #pragma unroll
    for (int mi = 0; mi < 4; mi++)
        #pragma unroll
        for (int ni = 0; ni < 4; ni++)
            #pragma unroll
            for (int r = 0; r < 4; r++) acc[mi][ni][r] = 0.f;

    float4 pa[4], pb[4];
    #pragma unroll
    for (int i = 0; i < 4; i++) {
        pa[i] = *reinterpret_cast<const float4*>(A  + (size_t)(rowBase + lrow[i]) * lda + lcol[i]);
        pb[i] = *reinterpret_cast<const float4*>(Bw + (size_t)(colBase + lrow[i]) * ldb + lcol[i]);
    }
    #pragma unroll
    for (int i = 0; i < 4; i++) {
        float* da = &As[lrow[i]][lcol[i]];
        da[0] = to_tf32(pa[i].x); da[1] = to_tf32(pa[i].y);
        da[2] = to_tf32(pa[i].z); da[3] = to_tf32(pa[i].w);
        float* db = &Bs[lrow[i]][lcol[i]];
        db[0] = to_tf32(pb[i].x); db[1] = to_tf32(pb[i].y);
        db[2] = to_tf32(pb[i].z); db[3] = to_tf32(pb[i].w);
    }
    __syncthreads();

    for (int k0 = 0; k0 < K; k0 += 32) {
        const bool has = (k0 + 32) < K;
        if (has) {
            #pragma unroll
            for (int i = 0; i < 4; i++) {
                pa[i] = *reinterpret_cast<const float4*>(A  + (size_t)(rowBase + lrow[i]) * lda + k0 + 32 + lcol[i]);
                pb[i] = *reinterpret_cast<const float4*>(Bw + (size_t)(colBase + lrow[i]) * ldb + k0 + 32 + lcol[i]);
            }
        }
        #pragma unroll
        for (int ks = 0; ks < 4; ks++) {
            const uint32_t koff = ks * 32;
            uint32_t a[4][4], b[2][4];
            #pragma unroll
            for (int mi = 0; mi < 4; mi++)
                LDSM_X4(a[mi][0], a[mi][1], a[mi][2], a[mi][3], aAddr[mi] + koff);
            #pragma unroll
            for (int p = 0; p < 2; p++)
                LDSM_X4(b[p][0], b[p][1], b[p][2], b[p][3], bAddr[p] + koff);
            #pragma unroll
            for (int mi = 0; mi < 4; mi++)
                #pragma unroll
                for (int ni = 0; ni < 4; ni++) {
                    const int p = ni >> 1, o = (ni & 1) << 1;
                    MMA_TF32(acc[mi][ni], a[mi], b[p][o], b[p][o + 1]);
                }
        }
        __syncthreads();
        if (has) {
            #pragma unroll
            for (int i = 0; i < 4; i++) {
                float* da = &As[lrow[i]][lcol[i]];
                da[0] = to_tf32(pa[i].x); da[1] = to_tf32(pa[i].y);
                da[2] = to_tf32(pa[i].z); da[3] = to_tf32(pa[i].w);
                float* db = &Bs[lrow[i]][lcol[i]];
                db[0] = to_tf32(pb[i].x); db[1] = to_tf32(pb[i].y);
                db[2] = to_tf32(pb[i].z); db[3] = to_tf32(pb[i].w);
            }
            __syncthreads();
        }
    }

    const int erow = rowBase + wm * 64 + (lane >> 2);
    const int ecol = colBase + wn * 32 + ((lane & 3) << 1);
    #pragma unroll
    for (int mi = 0; mi < 4; mi++) {
        #pragma unroll
        for (int ni = 0; ni < 4; ni++) {
            const int r = erow + mi * 16;
            const int c = ecol + ni * 8;
            float2 add = make_float2(0.f, 0.f);
            if (bias) {
                float2 bb = *reinterpret_cast<const float2*>(bias + c);
                add.x += bb.x; add.y += bb.y;
            }
            float2 v0, v1;
            v0.x = acc[mi][ni][0] + add.x;
            v0.y = acc[mi][ni][1] + add.y;
            v1.x = acc[mi][ni][2] + add.x;
            v1.y = acc[mi][ni][3] + add.y;
            if (resid) {
                float2 r0 = *reinterpret_cast<const float2*>(resid + (size_t)r * ldc + c);
                float2 r1 = *reinterpret_cast<const float2*>(resid + (size_t)(r + 8) * ldc + c);
                v0.x += r0.x; v0.y += r0.y;
                v1.x += r1.x; v1.y += r1.y;
            }
            *reinterpret_cast<float2*>(C + (size_t)r * ldc + c)       = v0;
            *reinterpret_cast<float2*>(C + (size_t)(r + 8) * ldc + c) = v1;
        }
    }
}

// ----------------------------------------------------------------------------
// Fused attention: per block = 128 q-rows of one (b,h).
// Streams 16 K-chunks of 128 keys: TF32 MMA -> scores in smem -> online
// max/sum + exact streaming top-20 (sorted list across lanes 0..19) -> AV.
// S is never materialized in global memory.
// ----------------------------------------------------------------------------
#define QS_ST 68
#define KS_ST 68
#define SS_ST 132
// float offsets into dynamic smem
#define OFF_QS 0
#define OFF_KS (128 * QS_ST)                       // 2 buffers
#define OFF_SS (OFF_KS + 2 * 128 * KS_ST)
#define OFF_LV (OFF_SS + 128 * SS_ST)
#define OFF_LI (OFF_LV + 128 * NTOPK)
#define OFF_MS (OFF_LI + 128 * NTOPK)
#define OFF_LS (OFF_MS + 128)
#define SMEM_FLOATS (OFF_LS + 128)
#define SMEM_BYTES (SMEM_FLOATS * 4)

__global__ __launch_bounds__(256, 1)
void fused_attn()
{
    extern __shared__ float sm[];
    float (*Qs)[QS_ST] = reinterpret_cast<float(*)[QS_ST]>(sm + OFF_QS);
    float (*Ss)[SS_ST] = reinterpret_cast<float(*)[SS_ST]>(sm + OFF_SS);
    float* Lv = sm + OFF_LV;
    int*   Li = reinterpret_cast<int*>(sm + OFF_LI);
    float* Ms = sm + OFF_MS;
    float* Ls = sm + OFF_LS;

    const int tid  = threadIdx.x;
    const int lane = tid & 31;
    const int wid  = tid >> 5;
    const int q0   = blockIdx.x * 128;
    const int bh   = blockIdx.y;
    const int b    = bh >> 3;
    const int h    = bh & 7;

    const float* Qg = g_Q + (size_t)b * NLQ * NE + h * NHD;
    const float* Kg = g_K + (size_t)b * NLK * NE + h * NHD;
    const float* Vg = g_V + (size_t)b * NLK * NE + h * NHD;

    // ---- load Q tile once (scale 1/8 folded in: exact power-of-2) ----
    #pragma unroll
    for (int i = 0; i < 8; i++) {
        int f = tid + (i << 8);
        int r = f >> 4, c4 = (f & 15) << 2;
        float4 t = *reinterpret_cast<const float4*>(Qg + (size_t)(q0 + r) * NE + c4);
        float* d = &Qs[r][c4];
        d[0] = to_tf32(0.125f * t.x); d[1] = to_tf32(0.125f * t.y);
        d[2] = to_tf32(0.125f * t.z); d[3] = to_tf32(0.125f * t.w);
    }
    // ---- init state ----
    for (int idx = tid; idx < 128 * NTOPK; idx += 256) {
        Lv[idx] = -FLT_MAX;
        Li[idx] = 0x7fffffff;
    }
    if (tid < 128) { Ms[tid] = -FLT_MAX; Ls[tid] = 0.f; }

    // ---- prologue: K chunk 0 -> buffer 0 ----
    float4 kp[8];
    #pragma unroll
    for (int i = 0; i < 8; i++) {
        int f = tid + (i << 8);
        int r = f >> 4, c4 = (f & 15) << 2;
        kp[i] = *reinterpret_cast<const float4*>(Kg + (size_t)r * NE + c4);
    }
    {
        float (*Kb)[KS_ST] = reinterpret_cast<float(*)[KS_ST]>(sm + OFF_KS);
        #pragma unroll
        for (int i = 0; i < 8; i++) {
            int f = tid + (i << 8);
            int r = f >> 4, c4 = (f & 15) << 2;
            float* d = &Kb[r][c4];
            d[0] = to_tf32(kp[i].x); d[1] = to_tf32(kp[i].y);
            d[2] = to_tf32(kp[i].z); d[3] = to_tf32(kp[i].w);
        }
    }
    __syncthreads();

    // ---- MMA fragment addresses ----
    const int wm = wid >> 2, wn = wid & 3;
    const int arow = wm * 64 + (lane & 15);
    const int acol = (lane >> 4) << 2;
    uint32_t aAddr[4];
    #pragma unroll
    for (int mi = 0; mi < 4; mi++)
        aAddr[mi] = smem_u32(&Qs[arow + mi * 16][acol]);
    const int brow = wn * 32 + ((lane >> 4) << 3) + (lane & 7);
    const int bcol = ((lane >> 3) & 1) << 2;
    uint32_t bAddr[2][2];
    #pragma unroll
    for (int buf = 0; buf < 2; buf++) {
        float (*Kb)[KS_ST] = reinterpret_cast<float(*)[KS_ST]>(sm + OFF_KS + buf * 128 * KS_ST);
        #pragma unroll
        for (int p = 0; p < 2; p++)
            bAddr[buf][p] = smem_u32(&Kb[brow + p * 16][bcol]);
    }

    for (int c = 0; c < 16; c++) {
        // ---- MMA: 128x128 scores of chunk c ----
        float acc[4][4][4];
        #pragma unroll
        for (int mi = 0; mi < 4; mi++)
            #pragma unroll
            for (int ni = 0; ni < 4; ni++)
                #pragma unroll
                for (int r = 0; r < 4; r++) acc[mi][ni][r] = 0.f;

        const int buf = c & 1;
        #pragma unroll
        for (int ks = 0; ks < 8; ks++) {
            const uint32_t koff = ks * 32;
            uint32_t a[4][4], bf[2][4];
            #pragma unroll
            for (int mi = 0; mi < 4; mi++)
                LDSM_X4(a[mi][0], a[mi][1], a[mi][2], a[mi][3], aAddr[mi] + koff);
            #pragma unroll
            for (int p = 0; p < 2; p++)
                LDSM_X4(bf[p][0], bf[p][1], bf[p][2], bf[p][3], bAddr[buf][p] + koff);
            #pragma unroll
            for (int mi = 0; mi < 4; mi++)
                #pragma unroll
                for (int ni = 0; ni < 4; ni++) {
                    const int p = ni >> 1, o = (ni & 1) << 1;
                    MMA_TF32(acc[mi][ni], a[mi], bf[p][o], bf[p][o + 1]);
                }
        }

        // ---- prefetch K chunk c+1 ----
        const bool has = (c < 15);
        if (has) {
            #pragma unroll
            for (int i = 0; i < 8; i++) {
                int f = tid + (i << 8);
                int r = f >> 4, c4 = (f & 15) << 2;
                kp[i] = *reinterpret_cast<const float4*>(Kg + (size_t)((c + 1) * 128 + r) * NE + c4);
            }
        }
        __syncthreads();   // (1) prior selection done: Ss free; Ks[buf^1] free

        // ---- store scores to smem ----
        const int erow = wm * 64 + (lane >> 2);
        const int ecol = wn * 32 + ((lane & 3) << 1);
        #pragma unroll
        for (int mi = 0; mi < 4; mi++) {
            #pragma unroll
            for (int ni = 0; ni < 4; ni++) {
                const int r = erow + mi * 16;
                const int cc = ecol + ni * 8;
                Ss[r][cc]         = acc[mi][ni][0];
                Ss[r][cc + 1]     = acc[mi][ni][1];
                Ss[r + 8][cc]     = acc[mi][ni][2];
                Ss[r + 8][cc + 1] = acc[mi][ni][3];
            }
        }
        if (has) {
            float (*Kb)[KS_ST] = reinterpret_cast<float(*)[KS_ST]>(sm + OFF_KS + (buf ^ 1) * 128 * KS_ST);
            #pragma unroll
            for (int i = 0; i < 8; i++) {
                int f = tid + (i << 8);
                int r = f >> 4, c4 = (f & 15) << 2;
                float* d = &Kb[r][c4];
                d[0] = to_tf32(kp[i].x); d[1] = to_tf32(kp[i].y);
                d[2] = to_tf32(kp[i].z); d[3] = to_tf32(kp[i].w);
            }
        }
        __syncthreads();   // (2) Ss + next K buffer ready

        // ---- selection: each warp owns rows [wid*16, wid*16+16) ----
        const int k0 = c << 7;
        for (int rr = 0; rr < 16; rr++) {
            const int r = (wid << 4) + rr;
            float lv = (lane < NTOPK) ? Lv[r * NTOPK + lane] : -FLT_MAX;
            int   li = (lane < NTOPK) ? Li[r * NTOPK + lane] : 0x7fffffff;
            float minV = __shfl_sync(FULL, lv, NTOPK - 1);

            float v[4];
            #pragma unroll
            for (int i = 0; i < 4; i++) v[i] = Ss[r][lane + (i << 5)];

            // online max / sum(exp)
            float mc = fmaxf(fmaxf(v[0], v[1]), fmaxf(v[2], v[3]));
            #pragma unroll
            for (int off = 16; off > 0; off >>= 1)
                mc = fmaxf(mc, __shfl_xor_sync(FULL, mc, off));
            const float m_old = Ms[r];
            const float m_new = fmaxf(m_old, mc);
            float e = expf(v[0] - m_new) + expf(v[1] - m_new)
                    + expf(v[2] - m_new) + expf(v[3] - m_new);
            #pragma unroll
            for (int off = 16; off > 0; off >>= 1)
                e += __shfl_xor_sync(FULL, e, off);
            if (lane == 0) {
                Ms[r] = m_new;
                Ls[r] = Ls[r] * expf(m_old - m_new) + e;
            }

            // streaming insert into sorted top-20 (val desc, idx asc)
            #pragma unroll
            for (int i = 0; i < 4; i++) {
                float cv   = v[i];
                int   cidx = k0 + lane + (i << 5);
                while (true) {
                    unsigned mask = __ballot_sync(FULL, cv > minV);
                    if (!mask) break;
                    const int src = __ffs(mask) - 1;
                    const float bv = __shfl_sync(FULL, cv, src);
                    const int   bi = __shfl_sync(FULL, cidx, src);
                    unsigned gt = __ballot_sync(FULL,
                        (lane < NTOPK) && (lv > bv || (lv == bv && li < bi)));
                    const int pos = __popc(gt);
                    const float upv = __shfl_up_sync(FULL, lv, 1);
                    const int   upi = __shfl_up_sync(FULL, li, 1);
                    if (lane < NTOPK) {
                        if (lane == pos)      { lv = bv;  li = bi;  }
                        else if (lane > pos)  { lv = upv; li = upi; }
                    }
                    minV = __shfl_sync(FULL, lv, NTOPK - 1);
                    if (lane == src) cv = -FLT_MAX;
                }
            }
            if (lane < NTOPK) {
                Lv[r * NTOPK + lane] = lv;
                Li[r * NTOPK + lane] = li;
            }
        }
    }
    __syncthreads();

    // ---- epilogue: probs + sparse AV ----
    for (int rr = 0; rr < 16; rr++) {
        const int r = (wid << 4) + rr;
        const float gm = Ms[r];
        const float denom = Ls[r];
        float lv = (lane < NTOPK) ? Lv[r * NTOPK + lane] : 0.f;
        int   li = (lane < NTOPK) ? Li[r * NTOPK + lane] : 0;
        const float p = (lane < NTOPK) ? expf(lv - gm) / denom : 0.f;
        float a0 = 0.f, a1 = 0.f;
        #pragma unroll
        for (int j = 0; j < NTOPK; j++) {
            const float pj = __shfl_sync(FULL, p, j);
            const int   ij = __shfl_sync(FULL, li, j);
            const float* vp = Vg + (size_t)ij * NE;
            a0 = fmaf(pj, vp[lane], a0);
            a1 = fmaf(pj, vp[lane + 32], a1);
        }
        float* op = g_O + (size_t)(b * NLQ + q0 + r) * NE + h * NHD;
        op[lane]      = a0;
        op[lane + 32] = a1;
    }
}

// ----------------------------------------------------------------------------
extern "C" void kernel_launch(void* const* d_in, const int* in_sizes, int n_in,
                              void* d_out, int out_size)
{
    const float* q  = (const float*)d_in[0];
    const float* k  = (const float*)d_in[1];
    const float* v  = (const float*)d_in[2];
    const float* Wq = (const float*)d_in[3];
    const float* Wk = (const float*)d_in[4];
    const float* Wv = (const float*)d_in[5];
    const float* Wo = (const float*)d_in[6];
    const float* bo = (const float*)d_in[7];
    float* out = (float*)d_out;

    float *gQ, *gK, *gV, *gO;
    cudaGetSymbolAddress((void**)&gQ, g_Q);
    cudaGetSymbolAddress((void**)&gK, g_K);
    cudaGetSymbolAddress((void**)&gV, g_V);
    cudaGetSymbolAddress((void**)&gO, g_O);

    cudaFuncSetAttribute(fused_attn, cudaFuncAttributeMaxDynamicSharedMemorySize,
                         SMEM_BYTES);

    dim3 blk(256);

    // Q = q @ Wq^T
    gemm_tf32<<<dim3(NE / 128, (NB * NLQ) / 128), blk>>>(
        q, Wq, gQ, NE, NE, NE, NE, nullptr, nullptr);

    // K = k @ Wk^T
    gemm_tf32<<<dim3(NE / 128, (NB * NLK) / 128), blk>>>(
        k, Wk, gK, NE, NE, NE, NE, nullptr, nullptr);

    // V = v @ Wv^T
    gemm_tf32<<<dim3(NE / 128, (NB * NLK) / 128), blk>>>(
        v, Wv, gV, NE, NE, NE, NE, nullptr, nullptr);

    // fused scores + softmax + top-20 + AV
    fused_attn<<<dim3(NLQ / 128, NB * NH), blk, SMEM_BYTES>>>();

    // out = O @ Wo^T + bo + q
    gemm_tf32<<<dim3(NE / 128, (NB * NLQ) / 128), blk>>>(
        gO, Wo, out, NE, NE, NE, NE, bo, q);
}

// round 14
// speedup vs baseline: 2.1929x; 1.4658x over previous
#include <cuda_runtime.h>
#include <cfloat>
#include <math.h>
#include <stdint.h>

#define NB    8
#define NLQ   512
#define NLK   2048
#define NE    512
#define NH    8
#define NHD   64
#define NTOPK 20
#define FULL  0xffffffffu
#define CAP   512

// Scratch (allocation-free rule: __device__ globals)
__device__ float g_Q[(size_t)NB * NLQ * NE];             // 8 MB
__device__ float g_K[(size_t)NB * NLK * NE];             // 32 MB
__device__ float g_V[(size_t)NB * NLK * NE];             // 32 MB
__device__ float g_S[(size_t)NB * NH * NLQ * NLK];       // 256 MB
__device__ float g_O[(size_t)NB * NLQ * NE];             // 8 MB

__device__ __forceinline__ float to_tf32(float x) {
    uint32_t u;
    asm("cvt.rna.tf32.f32 %0, %1;" : "=r"(u) : "f"(x));
    return __uint_as_float(u);
}

__device__ __forceinline__ uint32_t smem_u32(const void* p) {
    return (uint32_t)__cvta_generic_to_shared(p);
}

#define LDSM_X4(R0, R1, R2, R3, ADDR)                                          \
    asm volatile("ldmatrix.sync.aligned.m8n8.x4.shared.b16 {%0,%1,%2,%3}, [%4];" \
                 : "=r"(R0), "=r"(R1), "=r"(R2), "=r"(R3) : "r"(ADDR))

#define MMA_TF32(C, A, B0, B1)                                                  \
    asm volatile("mma.sync.aligned.m16n8k8.row.col.f32.tf32.tf32.f32 "          \
                 "{%0,%1,%2,%3}, {%4,%5,%6,%7}, {%8,%9}, {%0,%1,%2,%3};"        \
                 : "+f"((C)[0]), "+f"((C)[1]), "+f"((C)[2]), "+f"((C)[3])       \
                 : "r"((A)[0]), "r"((A)[1]), "r"((A)[2]), "r"((A)[3]),          \
                   "r"(B0), "r"(B1))

// ----------------------------------------------------------------------------
// TF32 tensor-core GEMM (round-11 proven): C = alpha * A @ Bw^T (+bias+resid).
// 128x128 tile, BK=32, 256 threads, warp tile 64x32 (m16n8k8 atoms).
// Batched via blockIdx.z with (b,h)-decomposed strides.
// ----------------------------------------------------------------------------
__global__ __launch_bounds__(256, 2)
void gemm_tf32(const float* __restrict__ A, const float* __restrict__ Bw,
               float* __restrict__ C,
               int K, int lda, int ldb, int ldc, float alpha,
               size_t sAb, size_t sAh, size_t sBb, size_t sBh, size_t sCz, int hdiv,
               const float* __restrict__ bias, const float* __restrict__ resid)
{
    __shared__ float As[128][36];
    __shared__ float Bs[128][36];

    const int tid  = threadIdx.x;
    const int lane = tid & 31;
    const int wid  = tid >> 5;
    const int wm   = wid >> 2;
    const int wn   = wid & 3;
    const int rowBase = blockIdx.y * 128;
    const int colBase = blockIdx.x * 128;

    const int z  = blockIdx.z;
    const int zb = z / hdiv;
    const int zh = z - zb * hdiv;
    A  += (size_t)zb * sAb + (size_t)zh * sAh;
    Bw += (size_t)zb * sBb + (size_t)zh * sBh;
    C  += (size_t)z * sCz;

    int lrow[4], lcol[4];
    #pragma unroll
    for (int i = 0; i < 4; i++) {
        int f = tid + (i << 8);
        lrow[i] = f >> 3;
        lcol[i] = (f & 7) << 2;
    }

    const int arow = wm * 64 + (lane & 15);
    const int acol = (lane >> 4) << 2;
    uint32_t aAddr[4];
    #pragma unroll
    for (int mi = 0; mi < 4; mi++)
        aAddr[mi] = smem_u32(&As[arow + mi * 16][acol]);
    const int brow = wn * 32 + ((lane >> 4) << 3) + (lane & 7);
    const int bcol = ((lane >> 3) & 1) << 2;
    uint32_t bAddr[2];
    #pragma unroll
    for (int p = 0; p < 2; p++)
        bAddr[p] = smem_u32(&Bs[brow + p * 16][bcol]);

    float acc[4][4][4];
    #pragma unroll
    for (int mi = 0; mi < 4; mi++)
        #pragma unroll
        for (int ni = 0; ni < 4; ni++)
            #pragma unroll
            for (int r = 0; r < 4; r++) acc[mi][ni][r] = 0.f;

    float4 pa[4], pb[4];
    #pragma unroll
    for (int i = 0; i < 4; i++) {
        pa[i] = *reinterpret_cast<const float4*>(A  + (size_t)(rowBase + lrow[i]) * lda + lcol[i]);
        pb[i] = *reinterpret_cast<const float4*>(Bw + (size_t)(colBase + lrow[i]) * ldb + lcol[i]);
    }
    #pragma unroll
    for (int i = 0; i < 4; i++) {
        float* da = &As[lrow[i]][lcol[i]];
        da[0] = to_tf32(pa[i].x); da[1] = to_tf32(pa[i].y);
        da[2] = to_tf32(pa[i].z); da[3] = to_tf32(pa[i].w);
        float* db = &Bs[lrow[i]][lcol[i]];
        db[0] = to_tf32(pb[i].x); db[1] = to_tf32(pb[i].y);
        db[2] = to_tf32(pb[i].z); db[3] = to_tf32(pb[i].w);
    }
    __syncthreads();

    for (int k0 = 0; k0 < K; k0 += 32) {
        const bool has = (k0 + 32) < K;
        if (has) {
            #pragma unroll
            for (int i = 0; i < 4; i++) {
                pa[i] = *reinterpret_cast<const float4*>(A  + (size_t)(rowBase + lrow[i]) * lda + k0 + 32 + lcol[i]);
                pb[i] = *reinterpret_cast<const float4*>(Bw + (size_t)(colBase + lrow[i]) * ldb + k0 + 32 + lcol[i]);
            }
        }
        #pragma unroll
        for (int ks = 0; ks < 4; ks++) {
            const uint32_t koff = ks * 32;
            uint32_t a[4][4], b[2][4];
            #pragma unroll
            for (int mi = 0; mi < 4; mi++)
                LDSM_X4(a[mi][0], a[mi][1], a[mi][2], a[mi][3], aAddr[mi] + koff);
            #pragma unroll
            for (int p = 0; p < 2; p++)
                LDSM_X4(b[p][0], b[p][1], b[p][2], b[p][3], bAddr[p] + koff);
            #pragma unroll
            for (int mi = 0; mi < 4; mi++)
                #pragma unroll
                for (int ni = 0; ni < 4; ni++) {
                    const int p = ni >> 1, o = (ni & 1) << 1;
                    MMA_TF32(acc[mi][ni], a[mi], b[p][o], b[p][o + 1]);
                }
        }
        __syncthreads();
        if (has) {
            #pragma unroll
            for (int i = 0; i < 4; i++) {
                float* da = &As[lrow[i]][lcol[i]];
                da[0] = to_tf32(pa[i].x); da[1] = to_tf32(pa[i].y);
                da[2] = to_tf32(pa[i].z); da[3] = to_tf32(pa[i].w);
                float* db = &Bs[lrow[i]][lcol[i]];
                db[0] = to_tf32(pb[i].x); db[1] = to_tf32(pb[i].y);
                db[2] = to_tf32(pb[i].z); db[3] = to_tf32(pb[i].w);
            }
            __syncthreads();
        }
    }

    const int erow = rowBase + wm * 64 + (lane >> 2);
    const int ecol = colBase + wn * 32 + ((lane & 3) << 1);
    #pragma unroll
    for (int mi = 0; mi < 4; mi++) {
        #pragma unroll
        for (int ni = 0; ni < 4; ni++) {
            const int r = erow + mi * 16;
            const int c = ecol + ni * 8;
            float2 add = make_float2(0.f, 0.f);
            if (bias) {
                float2 bb = *reinterpret_cast<const float2*>(bias + c);
                add.x += bb.x; add.y += bb.y;
            }
            float2 v0, v1;
            v0.x = alpha * acc[mi][ni][0] + add.x;
            v0.y = alpha * acc[mi][ni][1] + add.y;
            v1.x = alpha * acc[mi][ni][2] + add.x;
            v1.y = alpha * acc[mi][ni][3] + add.y;
            if (resid) {
                float2 r0 = *reinterpret_cast<const float2*>(resid + (size_t)r * ldc + c);
                float2 r1 = *reinterpret_cast<const float2*>(resid + (size_t)(r + 8) * ldc + c);
                v0.x += r0.x; v0.y += r0.y;
                v1.x += r1.x; v1.y += r1.y;
            }
            *reinterpret_cast<float2*>(C + (size_t)r * ldc + c)       = v0;
            *reinterpret_cast<float2*>(C + (size_t)(r + 8) * ldc + c) = v1;
        }
    }
}

// ----------------------------------------------------------------------------
// Warp-per-row radix top-k + softmax + sparse AV.
// Each warp owns one score row (2048 floats, 64 regs/lane).
//   1. max + sum(exp) in registers
//   2. 8-bit histogram on monotone key -> threshold bin for the 20th value
//   3. 8-bit refinement within the bin -> 16-bit threshold (few candidates)
//   4. collect candidates, exact 20x warp-argmax (ties: lowest index)
//   5. p = exp(v-m)/sum for winners; AV gather -> g_O
// ----------------------------------------------------------------------------
__device__ __forceinline__ uint32_t fkey(float f) {
    uint32_t u = __float_as_uint(f);
    return (u & 0x80000000u) ? ~u : (u | 0x80000000u);
}

// find bin B with count(bins>B) < target <= count(bins>=B); returns cntAbove
__device__ __forceinline__ void hist_thresh(const int* h, int lane, int target,
                                            int& B, int& cntAbove)
{
    int c = 0;
    #pragma unroll
    for (int k = 0; k < 8; k++) c += h[lane * 8 + k];
    int S = c;
    #pragma unroll
    for (int off = 1; off < 32; off <<= 1) {
        int o = __shfl_down_sync(FULL, S, off);
        if (lane + off < 32) S += o;
    }
    int Snext = __shfl_down_sync(FULL, S, 1);
    if (lane == 31) Snext = 0;
    const bool isL = (S >= target) && (Snext < target);
    const unsigned ball = __ballot_sync(FULL, isL);
    const int L = __ffs(ball) - 1;
    int myB = 0, myC = 0;
    if (isL) {
        int cum = Snext;
        for (int bb = lane * 8 + 7; bb >= lane * 8; bb--) {
            if (cum + h[bb] >= target) { myB = bb; myC = cum; break; }
            cum += h[bb];
        }
    }
    B        = __shfl_sync(FULL, myB, L);
    cntAbove = __shfl_sync(FULL, myC, L);
}

__global__ __launch_bounds__(256)
void topk_av()
{
    __shared__ int   hist[8][256];
    __shared__ float lv[8][CAP];
    __shared__ int   li[8][CAP];
    __shared__ int   cnt[8];
    __shared__ float wv[8][NTOPK];
    __shared__ int   wi[8][NTOPK];

    const int lane = threadIdx.x & 31;
    const int wid  = threadIdx.x >> 5;
    const int row  = blockIdx.x * 8 + wid;     // (b*H+h)*LQ + q
    const int q    = row & (NLQ - 1);
    const int bh   = row >> 9;
    const int h    = bh & (NH - 1);
    const int b    = bh >> 3;

    const float* s = g_S + (size_t)row * NLK;

    // ---- load full row into registers (coalesced float4) ----
    float v[64];
    #pragma unroll
    for (int i = 0; i < 16; i++) {
        float4 t = *reinterpret_cast<const float4*>(s + i * 128 + lane * 4);
        v[i * 4 + 0] = t.x; v[i * 4 + 1] = t.y;
        v[i * 4 + 2] = t.z; v[i * 4 + 3] = t.w;
    }

    // ---- row max ----
    float m = v[0];
    #pragma unroll
    for (int i = 1; i < 64; i++) m = fmaxf(m, v[i]);
    #pragma unroll
    for (int off = 16; off > 0; off >>= 1)
        m = fmaxf(m, __shfl_xor_sync(FULL, m, off));

    // ---- row sum(exp) ----
    float ssum = 0.f;
    #pragma unroll
    for (int i = 0; i < 64; i++) ssum += __expf(v[i] - m);
    #pragma unroll
    for (int off = 16; off > 0; off >>= 1)
        ssum += __shfl_xor_sync(FULL, ssum, off);

    // ---- level-1 histogram (key bits [31:24]) ----
    int* hh = hist[wid];
    #pragma unroll
    for (int i = 0; i < 8; i++) hh[lane + i * 32] = 0;
    __syncwarp();
    #pragma unroll
    for (int i = 0; i < 64; i++)
        atomicAdd(&hh[fkey(v[i]) >> 24], 1);
    __syncwarp();

    int B1, cnt1;
    hist_thresh(hh, lane, NTOPK, B1, cnt1);

    // ---- level-2 histogram (key bits [23:16] within bin B1) ----
    __syncwarp();
    #pragma unroll
    for (int i = 0; i < 8; i++) hh[lane + i * 32] = 0;
    __syncwarp();
    #pragma unroll
    for (int i = 0; i < 64; i++) {
        const uint32_t k = fkey(v[i]);
        if ((k >> 24) == (uint32_t)B1) atomicAdd(&hh[(k >> 16) & 0xff], 1);
    }
    __syncwarp();

    int B2, cnt2;
    hist_thresh(hh, lane, NTOPK - cnt1, B2, cnt2);
    const uint32_t T16 = ((uint32_t)B1 << 8) | (uint32_t)B2;

    // ---- collect candidates with keytop16 >= T16 ----
    if (lane == 0) cnt[wid] = 0;
    __syncwarp();
    #pragma unroll
    for (int i = 0; i < 64; i++) {
        if ((fkey(v[i]) >> 16) >= T16) {
            const int p = atomicAdd(&cnt[wid], 1);
            if (p < CAP) {
                lv[wid][p] = v[i];
                li[wid][p] = (i >> 2) * 128 + (lane << 2) + (i & 3);
            }
        }
    }
    __syncwarp();
    const int n = cnt[wid];

    if (n <= CAP) {
        // ---- exact top-20 of candidates (val desc, idx asc) ----
        for (int t = 0; t < NTOPK; t++) {
            float bv = -FLT_MAX; int bi = 0x7fffffff; int bp = -1;
            for (int p = lane; p < n; p += 32) {
                const float xv = lv[wid][p];
                const int   xi = li[wid][p];
                if (xv > bv || (xv == bv && xi < bi)) { bv = xv; bi = xi; bp = p; }
            }
            #pragma unroll
            for (int off = 16; off > 0; off >>= 1) {
                const float ov = __shfl_xor_sync(FULL, bv, off);
                const int   oi = __shfl_xor_sync(FULL, bi, off);
                const int   op = __shfl_xor_sync(FULL, bp, off);
                if (ov > bv || (ov == bv && oi < bi)) { bv = ov; bi = oi; bp = op; }
            }
            if (lane == 0) { wv[wid][t] = bv; wi[wid][t] = bi; lv[wid][bp] = -FLT_MAX; }
            __syncwarp();
        }
    } else {
        // ---- pathological fallback: exact 20x argmax over registers ----
        for (int t = 0; t < NTOPK; t++) {
            float bv = -FLT_MAX; int bi = 0x7fffffff; int bs = -1;
            #pragma unroll
            for (int i = 0; i < 64; i++) {
                const int idx = (i >> 2) * 128 + (lane << 2) + (i & 3);
                if (v[i] > bv || (v[i] == bv && idx < bi)) { bv = v[i]; bi = idx; bs = i; }
            }
            const int myBi = bi;
            #pragma unroll
            for (int off = 16; off > 0; off >>= 1) {
                const float ov = __shfl_xor_sync(FULL, bv, off);
                const int   oi = __shfl_xor_sync(FULL, bi, off);
                if (ov > bv || (ov == bv && oi < bi)) { bv = ov; bi = oi; }
            }
            if (myBi == bi && bs >= 0) {
                #pragma unroll
                for (int i = 0; i < 64; i++) if (i == bs) v[i] = -FLT_MAX;
            }
            if (lane == 0) { wv[wid][t] = bv; wi[wid][t] = bi; }
        }
        __syncwarp();
    }

    // ---- probs + sparse AV ----
    const float p  = (lane < NTOPK) ? __expf(wv[wid][lane] - m) / ssum : 0.f;
    const int   ix = (lane < NTOPK) ? wi[wid][lane] : 0;
    const float* Vg = g_V + (size_t)b * NLK * NE + h * NHD;
    float a0 = 0.f, a1 = 0.f;
    #pragma unroll
    for (int j = 0; j < NTOPK; j++) {
        const float pj = __shfl_sync(FULL, p, j);
        const int   ij = __shfl_sync(FULL, ix, j);
        const float* vp = Vg + (size_t)ij * NE;
        a0 = fmaf(pj, vp[lane], a0);
        a1 = fmaf(pj, vp[lane + 32], a1);
    }
    float* op = g_O + (size_t)(b * NLQ + q) * NE + h * NHD;
    op[lane]      = a0;
    op[lane + 32] = a1;
}

// ----------------------------------------------------------------------------
extern "C" void kernel_launch(void* const* d_in, const int* in_sizes, int n_in,
                              void* d_out, int out_size)
{
    const float* q  = (const float*)d_in[0];
    const float* k  = (const float*)d_in[1];
    const float* v  = (const float*)d_in[2];
    const float* Wq = (const float*)d_in[3];
    const float* Wk = (const float*)d_in[4];
    const float* Wv = (const float*)d_in[5];
    const float* Wo = (const float*)d_in[6];
    const float* bo = (const float*)d_in[7];
    float* out = (float*)d_out;

    float *gQ, *gK, *gV, *gS, *gO;
    cudaGetSymbolAddress((void**)&gQ, g_Q);
    cudaGetSymbolAddress((void**)&gK, g_K);
    cudaGetSymbolAddress((void**)&gV, g_V);
    cudaGetSymbolAddress((void**)&gS, g_S);
    cudaGetSymbolAddress((void**)&gO, g_O);

    dim3 blk(256);

    // Q = q @ Wq^T
    gemm_tf32<<<dim3(NE / 128, (NB * NLQ) / 128, 1), blk>>>(
        q, Wq, gQ, NE, NE, NE, NE, 1.0f,
        0, 0, 0, 0, 0, 1, nullptr, nullptr);

    // K = k @ Wk^T
    gemm_tf32<<<dim3(NE / 128, (NB * NLK) / 128, 1), blk>>>(
        k, Wk, gK, NE, NE, NE, NE, 1.0f,
        0, 0, 0, 0, 0, 1, nullptr, nullptr);

    // V = v @ Wv^T
    gemm_tf32<<<dim3(NE / 128, (NB * NLK) / 128, 1), blk>>>(
        v, Wv, gV, NE, NE, NE, NE, 1.0f,
        0, 0, 0, 0, 0, 1, nullptr, nullptr);

    // S[b,h] = (1/8) * Q_h @ K_h^T
    gemm_tf32<<<dim3(NLK / 128, NLQ / 128, NB * NH), blk>>>(
        gQ, gK, gS, NHD, NE, NE, NLK, 0.125f,
        (size_t)NLQ * NE, (size_t)NHD,
        (size_t)NLK * NE, (size_t)NHD,
        (size_t)NLQ * NLK, NH,
        nullptr, nullptr);

    // warp-per-row radix top-20 + softmax + sparse AV
    topk_av<<<(NB * NH * NLQ) / 8, blk>>>();

    // out = O @ Wo^T + bo + q
    gemm_tf32<<<dim3(NE / 128, (NB * NLQ) / 128, 1), blk>>>(
        gO, Wo, out, NE, NE, NE, NE, 1.0f,
        0, 0, 0, 0, 0, 1, bo, q);
}

// round 15
// speedup vs baseline: 2.8436x; 1.2967x over previous
#include <cuda_runtime.h>
#include <cfloat>
#include <math.h>
#include <stdint.h>

#define NB    8
#define NLQ   512
#define NLK   2048
#define NE    512
#define NH    8
#define NHD   64
#define NTOPK 20
#define FULL  0xffffffffu
#define CAP   64

// Scratch (allocation-free rule: __device__ globals)
__device__ float g_Q[(size_t)NB * NLQ * NE];             // 8 MB
__device__ float g_K[(size_t)NB * NLK * NE];             // 32 MB
__device__ float g_V[(size_t)NB * NLK * NE];             // 32 MB
__device__ float g_S[(size_t)NB * NH * NLQ * NLK];       // 256 MB
__device__ float g_O[(size_t)NB * NLQ * NE];             // 8 MB

__device__ __forceinline__ float to_tf32(float x) {
    uint32_t u;
    asm("cvt.rna.tf32.f32 %0, %1;" : "=r"(u) : "f"(x));
    return __uint_as_float(u);
}

__device__ __forceinline__ uint32_t smem_u32(const void* p) {
    return (uint32_t)__cvta_generic_to_shared(p);
}

#define LDSM_X4(R0, R1, R2, R3, ADDR)                                          \
    asm volatile("ldmatrix.sync.aligned.m8n8.x4.shared.b16 {%0,%1,%2,%3}, [%4];" \
                 : "=r"(R0), "=r"(R1), "=r"(R2), "=r"(R3) : "r"(ADDR))

#define MMA_TF32(C, A, B0, B1)                                                  \
    asm volatile("mma.sync.aligned.m16n8k8.row.col.f32.tf32.tf32.f32 "          \
                 "{%0,%1,%2,%3}, {%4,%5,%6,%7}, {%8,%9}, {%0,%1,%2,%3};"        \
                 : "+f"((C)[0]), "+f"((C)[1]), "+f"((C)[2]), "+f"((C)[3])       \
                 : "r"((A)[0]), "r"((A)[1]), "r"((A)[2]), "r"((A)[3]),          \
                   "r"(B0), "r"(B1))

// ----------------------------------------------------------------------------
// TF32 tensor-core GEMM: C = alpha * A @ Bw^T (+bias+resid). 128x128 tile,
// BK=32, 256 threads, warp tile 64x32 (m16n8k8 atoms). Batched via blockIdx.z.
// ----------------------------------------------------------------------------
__global__ __launch_bounds__(256, 2)
void gemm_tf32(const float* __restrict__ A, const float* __restrict__ Bw,
               float* __restrict__ C,
               int K, int lda, int ldb, int ldc, float alpha,
               size_t sAb, size_t sAh, size_t sBb, size_t sBh, size_t sCz, int hdiv,
               const float* __restrict__ bias, const float* __restrict__ resid)
{
    __shared__ float As[128][36];
    __shared__ float Bs[128][36];

    const int tid  = threadIdx.x;
    const int lane = tid & 31;
    const int wid  = tid >> 5;
    const int wm   = wid >> 2;
    const int wn   = wid & 3;
    const int rowBase = blockIdx.y * 128;
    const int colBase = blockIdx.x * 128;

    const int z  = blockIdx.z;
    const int zb = z / hdiv;
    const int zh = z - zb * hdiv;
    A  += (size_t)zb * sAb + (size_t)zh * sAh;
    Bw += (size_t)zb * sBb + (size_t)zh * sBh;
    C  += (size_t)z * sCz;

    int lrow[4], lcol[4];
    #pragma unroll
    for (int i = 0; i < 4; i++) {
        int f = tid + (i << 8);
        lrow[i] = f >> 3;
        lcol[i] = (f & 7) << 2;
    }

    const int arow = wm * 64 + (lane & 15);
    const int acol = (lane >> 4) << 2;
    uint32_t aAddr[4];
    #pragma unroll
    for (int mi = 0; mi < 4; mi++)
        aAddr[mi] = smem_u32(&As[arow + mi * 16][acol]);
    const int brow = wn * 32 + ((lane >> 4) << 3) + (lane & 7);
    const int bcol = ((lane >> 3) & 1) << 2;
    uint32_t bAddr[2];
    #pragma unroll
    for (int p = 0; p < 2; p++)
        bAddr[p] = smem_u32(&Bs[brow + p * 16][bcol]);

    float acc[4][4][4];
    #pragma unroll
    for (int mi = 0; mi < 4; mi++)
        #pragma unroll
        for (int ni = 0; ni < 4; ni++)
            #pragma unroll
            for (int r = 0; r < 4; r++) acc[mi][ni][r] = 0.f;

    float4 pa[4], pb[4];
    #pragma unroll
    for (int i = 0; i < 4; i++) {
        pa[i] = *reinterpret_cast<const float4*>(A  + (size_t)(rowBase + lrow[i]) * lda + lcol[i]);
        pb[i] = *reinterpret_cast<const float4*>(Bw + (size_t)(colBase + lrow[i]) * ldb + lcol[i]);
    }
    #pragma unroll
    for (int i = 0; i < 4; i++) {
        float* da = &As[lrow[i]][lcol[i]];
        da[0] = to_tf32(pa[i].x); da[1] = to_tf32(pa[i].y);
        da[2] = to_tf32(pa[i].z); da[3] = to_tf32(pa[i].w);
        float* db = &Bs[lrow[i]][lcol[i]];
        db[0] = to_tf32(pb[i].x); db[1] = to_tf32(pb[i].y);
        db[2] = to_tf32(pb[i].z); db[3] = to_tf32(pb[i].w);
    }
    __syncthreads();

    for (int k0 = 0; k0 < K; k0 += 32) {
        const bool has = (k0 + 32) < K;
        if (has) {
            #pragma unroll
            for (int i = 0; i < 4; i++) {
                pa[i] = *reinterpret_cast<const float4*>(A  + (size_t)(rowBase + lrow[i]) * lda + k0 + 32 + lcol[i]);
                pb[i] = *reinterpret_cast<const float4*>(Bw + (size_t)(colBase + lrow[i]) * ldb + k0 + 32 + lcol[i]);
            }
        }
        #pragma unroll
        for (int ks = 0; ks < 4; ks++) {
            const uint32_t koff = ks * 32;
            uint32_t a[4][4], b[2][4];
            #pragma unroll
            for (int mi = 0; mi < 4; mi++)
                LDSM_X4(a[mi][0], a[mi][1], a[mi][2], a[mi][3], aAddr[mi] + koff);
            #pragma unroll
            for (int p = 0; p < 2; p++)
                LDSM_X4(b[p][0], b[p][1], b[p][2], b[p][3], bAddr[p] + koff);
            #pragma unroll
            for (int mi = 0; mi < 4; mi++)
                #pragma unroll
                for (int ni = 0; ni < 4; ni++) {
                    const int p = ni >> 1, o = (ni & 1) << 1;
                    MMA_TF32(acc[mi][ni], a[mi], b[p][o], b[p][o + 1]);
                }
        }
        __syncthreads();
        if (has) {
            #pragma unroll
            for (int i = 0; i < 4; i++) {
                float* da = &As[lrow[i]][lcol[i]];
                da[0] = to_tf32(pa[i].x); da[1] = to_tf32(pa[i].y);
                da[2] = to_tf32(pa[i].z); da[3] = to_tf32(pa[i].w);
                float* db = &Bs[lrow[i]][lcol[i]];
                db[0] = to_tf32(pb[i].x); db[1] = to_tf32(pb[i].y);
                db[2] = to_tf32(pb[i].z); db[3] = to_tf32(pb[i].w);
            }
            __syncthreads();
        }
    }

    const int erow = rowBase + wm * 64 + (lane >> 2);
    const int ecol = colBase + wn * 32 + ((lane & 3) << 1);
    #pragma unroll
    for (int mi = 0; mi < 4; mi++) {
        #pragma unroll
        for (int ni = 0; ni < 4; ni++) {
            const int r = erow + mi * 16;
            const int c = ecol + ni * 8;
            float2 add = make_float2(0.f, 0.f);
            if (bias) {
                float2 bb = *reinterpret_cast<const float2*>(bias + c);
                add.x += bb.x; add.y += bb.y;
            }
            float2 v0, v1;
            v0.x = alpha * acc[mi][ni][0] + add.x;
            v0.y = alpha * acc[mi][ni][1] + add.y;
            v1.x = alpha * acc[mi][ni][2] + add.x;
            v1.y = alpha * acc[mi][ni][3] + add.y;
            if (resid) {
                float2 r0 = *reinterpret_cast<const float2*>(resid + (size_t)r * ldc + c);
                float2 r1 = *reinterpret_cast<const float2*>(resid + (size_t)(r + 8) * ldc + c);
                v0.x += r0.x; v0.y += r0.y;
                v1.x += r1.x; v1.y += r1.y;
            }
            *reinterpret_cast<float2*>(C + (size_t)r * ldc + c)       = v0;
            *reinterpret_cast<float2*>(C + (size_t)(r + 8) * ldc + c) = v1;
        }
    }
}

// ----------------------------------------------------------------------------
// Warp-per-row radix top-k + softmax + sparse AV.
//   1. max + sum(exp) in registers
//   2. two-level 8-bit histogram -> 16-bit threshold for the 20th value
//   3. collect candidates (~20-25), warp bitonic sort of 32 packed 64-bit keys
//      (value desc, index asc) -> exact top-20; exact fallbacks for n>32.
//   4. p = exp(v-m)/sum; sparse AV gather -> g_O
// ----------------------------------------------------------------------------
__device__ __forceinline__ uint32_t fkey(float f) {
    uint32_t u = __float_as_uint(f);
    return (u & 0x80000000u) ? ~u : (u | 0x80000000u);
}
__device__ __forceinline__ float fkey_inv(uint32_t k) {
    uint32_t u = (k & 0x80000000u) ? (k ^ 0x80000000u) : ~k;
    return __uint_as_float(u);
}

// find bin B with count(bins>B) < target <= count(bins>=B); returns cntAbove
__device__ __forceinline__ void hist_thresh(const int* h, int lane, int target,
                                            int& B, int& cntAbove)
{
    int c = 0;
    #pragma unroll
    for (int k = 0; k < 8; k++) c += h[lane * 8 + k];
    int S = c;
    #pragma unroll
    for (int off = 1; off < 32; off <<= 1) {
        int o = __shfl_down_sync(FULL, S, off);
        if (lane + off < 32) S += o;
    }
    int Snext = __shfl_down_sync(FULL, S, 1);
    if (lane == 31) Snext = 0;
    const bool isL = (S >= target) && (Snext < target);
    const unsigned ball = __ballot_sync(FULL, isL);
    const int L = __ffs(ball) - 1;
    int myB = 0, myC = 0;
    if (isL) {
        int cum = Snext;
        for (int bb = lane * 8 + 7; bb >= lane * 8; bb--) {
            if (cum + h[bb] >= target) { myB = bb; myC = cum; break; }
            cum += h[bb];
        }
    }
    B        = __shfl_sync(FULL, myB, L);
    cntAbove = __shfl_sync(FULL, myC, L);
}

__global__ __launch_bounds__(256)
void topk_av()
{
    __shared__ int   hist[8][256];
    __shared__ float lv[8][CAP];
    __shared__ int   li[8][CAP];
    __shared__ int   cnt[8];
    __shared__ float wv[8][NTOPK];
    __shared__ int   wi[8][NTOPK];

    const int lane = threadIdx.x & 31;
    const int wid  = threadIdx.x >> 5;
    const int row  = blockIdx.x * 8 + wid;     // (b*H+h)*LQ + q
    const int q    = row & (NLQ - 1);
    const int bh   = row >> 9;
    const int h    = bh & (NH - 1);
    const int b    = bh >> 3;

    const float* s = g_S + (size_t)row * NLK;

    // ---- load full row into registers (coalesced float4) ----
    float v[64];
    #pragma unroll
    for (int i = 0; i < 16; i++) {
        float4 t = *reinterpret_cast<const float4*>(s + i * 128 + lane * 4);
        v[i * 4 + 0] = t.x; v[i * 4 + 1] = t.y;
        v[i * 4 + 2] = t.z; v[i * 4 + 3] = t.w;
    }

    // ---- row max ----
    float m = v[0];
    #pragma unroll
    for (int i = 1; i < 64; i++) m = fmaxf(m, v[i]);
    #pragma unroll
    for (int off = 16; off > 0; off >>= 1)
        m = fmaxf(m, __shfl_xor_sync(FULL, m, off));

    // ---- row sum(exp) ----
    float ssum = 0.f;
    #pragma unroll
    for (int i = 0; i < 64; i++) ssum += __expf(v[i] - m);
    #pragma unroll
    for (int off = 16; off > 0; off >>= 1)
        ssum += __shfl_xor_sync(FULL, ssum, off);

    // ---- level-1 histogram (key bits [31:24]) ----
    int* hh = hist[wid];
    #pragma unroll
    for (int i = 0; i < 8; i++) hh[lane + i * 32] = 0;
    __syncwarp();
    #pragma unroll
    for (int i = 0; i < 64; i++)
        atomicAdd(&hh[fkey(v[i]) >> 24], 1);
    __syncwarp();

    int B1, cnt1;
    hist_thresh(hh, lane, NTOPK, B1, cnt1);

    // ---- level-2 histogram (key bits [23:16] within bin B1) ----
    __syncwarp();
    #pragma unroll
    for (int i = 0; i < 8; i++) hh[lane + i * 32] = 0;
    __syncwarp();
    #pragma unroll
    for (int i = 0; i < 64; i++) {
        const uint32_t k = fkey(v[i]);
        if ((k >> 24) == (uint32_t)B1) atomicAdd(&hh[(k >> 16) & 0xff], 1);
    }
    __syncwarp();

    int B2, cnt2;
    hist_thresh(hh, lane, NTOPK - cnt1, B2, cnt2);
    const uint32_t T16 = ((uint32_t)B1 << 8) | (uint32_t)B2;

    // ---- collect candidates with keytop16 >= T16 (count >= 20 guaranteed) ----
    if (lane == 0) cnt[wid] = 0;
    __syncwarp();
    #pragma unroll
    for (int i = 0; i < 64; i++) {
        if ((fkey(v[i]) >> 16) >= T16) {
            const int p = atomicAdd(&cnt[wid], 1);
            if (p < CAP) {
                lv[wid][p] = v[i];
                li[wid][p] = (i >> 2) * 128 + (lane << 2) + (i & 3);
            }
        }
    }
    __syncwarp();
    const int n = cnt[wid];

    float topv = 0.f;
    int   topi = 0;

    if (n <= 32) {
        // ---- warp bitonic sort of 32 packed keys (val desc, idx asc) ----
        unsigned long long key = 0ULL;
        if (lane < n) {
            key = ((unsigned long long)fkey(lv[wid][lane]) << 32)
                | (uint32_t)(~li[wid][lane]);
        }
        #pragma unroll
        for (int k = 2; k <= 32; k <<= 1) {
            #pragma unroll
            for (int j = k >> 1; j > 0; j >>= 1) {
                const unsigned long long o = __shfl_xor_sync(FULL, key, j);
                const bool dirDesc = ((lane & k) == 0);
                const bool lower   = ((lane & j) == 0);
                const bool keepMax = (dirDesc == lower);
                key = keepMax ? (key > o ? key : o) : (key < o ? key : o);
            }
        }
        topv = fkey_inv((uint32_t)(key >> 32));
        topi = (int)(~(uint32_t)key);
    } else if (n <= CAP) {
        // ---- fallback: exact 20x argmax over smem candidates ----
        for (int t = 0; t < NTOPK; t++) {
            float bv = -FLT_MAX; int bi = 0x7fffffff; int bp = -1;
            for (int p = lane; p < n; p += 32) {
                const float xv = lv[wid][p];
                const int   xi = li[wid][p];
                if (xv > bv || (xv == bv && xi < bi)) { bv = xv; bi = xi; bp = p; }
            }
            #pragma unroll
            for (int off = 16; off > 0; off >>= 1) {
                const float ov = __shfl_xor_sync(FULL, bv, off);
                const int   oi = __shfl_xor_sync(FULL, bi, off);
                const int   op = __shfl_xor_sync(FULL, bp, off);
                if (ov > bv || (ov == bv && oi < bi)) { bv = ov; bi = oi; bp = op; }
            }
            if (lane == 0) { wv[wid][t] = bv; wi[wid][t] = bi; lv[wid][bp] = -FLT_MAX; }
            __syncwarp();
        }
        if (lane < NTOPK) { topv = wv[wid][lane]; topi = wi[wid][lane]; }
    } else {
        // ---- pathological fallback: exact 20x argmax over registers ----
        for (int t = 0; t < NTOPK; t++) {
            float bv = -FLT_MAX; int bi = 0x7fffffff; int bs = -1;
            #pragma unroll
            for (int i = 0; i < 64; i++) {
                const int idx = (i >> 2) * 128 + (lane << 2) + (i & 3);
                if (v[i] > bv || (v[i] == bv && idx < bi)) { bv = v[i]; bi = idx; bs = i; }
            }
            const int myBi = bi;
            #pragma unroll
            for (int off = 16; off > 0; off >>= 1) {
                const float ov = __shfl_xor_sync(FULL, bv, off);
                const int   oi = __shfl_xor_sync(FULL, bi, off);
                if (ov > bv || (ov == bv && oi < bi)) { bv = ov; bi = oi; }
            }
            if (myBi == bi && bs >= 0) {
                #pragma unroll
                for (int i = 0; i < 64; i++) if (i == bs) v[i] = -FLT_MAX;
            }
            if (lane == 0) { wv[wid][t] = bv; wi[wid][t] = bi; }
        }
        __syncwarp();
        if (lane < NTOPK) { topv = wv[wid][lane]; topi = wi[wid][lane]; }
    }

    // ---- probs + sparse AV ----
    const float p  = (lane < NTOPK) ? __expf(topv - m) / ssum : 0.f;
    const int   ix = (lane < NTOPK) ? topi : 0;
    const float* Vg = g_V + (size_t)b * NLK * NE + h * NHD;
    float a0 = 0.f, a1 = 0.f;
    #pragma unroll
    for (int j = 0; j < NTOPK; j++) {
        const float pj = __shfl_sync(FULL, p, j);
        const int   ij = __shfl_sync(FULL, ix, j);
        const float* vp = Vg + (size_t)ij * NE;
        a0 = fmaf(pj, vp[lane], a0);
        a1 = fmaf(pj, vp[lane + 32], a1);
    }
    float* op = g_O + (size_t)(b * NLQ + q) * NE + h * NHD;
    op[lane]      = a0;
    op[lane + 32] = a1;
}

// ----------------------------------------------------------------------------
extern "C" void kernel_launch(void* const* d_in, const int* in_sizes, int n_in,
                              void* d_out, int out_size)
{
    const float* q  = (const float*)d_in[0];
    const float* k  = (const float*)d_in[1];
    const float* v  = (const float*)d_in[2];
    const float* Wq = (const float*)d_in[3];
    const float* Wk = (const float*)d_in[4];
    const float* Wv = (const float*)d_in[5];
    const float* Wo = (const float*)d_in[6];
    const float* bo = (const float*)d_in[7];
    float* out = (float*)d_out;

    float *gQ, *gK, *gV, *gS, *gO;
    cudaGetSymbolAddress((void**)&gQ, g_Q);
    cudaGetSymbolAddress((void**)&gK, g_K);
    cudaGetSymbolAddress((void**)&gV, g_V);
    cudaGetSymbolAddress((void**)&gS, g_S);
    cudaGetSymbolAddress((void**)&gO, g_O);

    dim3 blk(256);

    // Q = q @ Wq^T
    gemm_tf32<<<dim3(NE / 128, (NB * NLQ) / 128, 1), blk>>>(
        q, Wq, gQ, NE, NE, NE, NE, 1.0f,
        0, 0, 0, 0, 0, 1, nullptr, nullptr);

    // K = k @ Wk^T
    gemm_tf32<<<dim3(NE / 128, (NB * NLK) / 128, 1), blk>>>(
        k, Wk, gK, NE, NE, NE, NE, 1.0f,
        0, 0, 0, 0, 0, 1, nullptr, nullptr);

    // V = v @ Wv^T
    gemm_tf32<<<dim3(NE / 128, (NB * NLK) / 128, 1), blk>>>(
        v, Wv, gV, NE, NE, NE, NE, 1.0f,
        0, 0, 0, 0, 0, 1, nullptr, nullptr);

    // S[b,h] = (1/8) * Q_h @ K_h^T
    gemm_tf32<<<dim3(NLK / 128, NLQ / 128, NB * NH), blk>>>(
        gQ, gK, gS, NHD, NE, NE, NLK, 0.125f,
        (size_t)NLQ * NE, (size_t)NHD,
        (size_t)NLK * NE, (size_t)NHD,
        (size_t)NLQ * NLK, NH,
        nullptr, nullptr);

    // warp-per-row radix top-20 + softmax + sparse AV
    topk_av<<<(NB * NH * NLQ) / 8, blk>>>();

    // out = O @ Wo^T + bo + q
    gemm_tf32<<<dim3(NE / 128, (NB * NLQ) / 128, 1), blk>>>(
        gO, Wo, out, NE, NE, NE, NE, 1.0f,
        0, 0, 0, 0, 0, 1, bo, q);
}

// round 16
// speedup vs baseline: 3.1330x; 1.1018x over previous
#include <cuda_runtime.h>
#include <cfloat>
#include <math.h>
#include <stdint.h>

#define NB    8
#define NLQ   512
#define NLK   2048
#define NE    512
#define NH    8
#define NHD   64
#define NTOPK 20
#define FULL  0xffffffffu
#define CAP   64

// Scratch (allocation-free rule: __device__ globals)
__device__ float g_Q[(size_t)NB * NLQ * NE];             // 8 MB
__device__ float g_K[(size_t)NB * NLK * NE];             // 32 MB
__device__ float g_V[(size_t)NB * NLK * NE];             // 32 MB
__device__ float g_S[(size_t)NB * NH * NLQ * NLK];       // 256 MB
__device__ float g_O[(size_t)NB * NLQ * NE];             // 8 MB

__device__ __forceinline__ float to_tf32(float x) {
    uint32_t u;
    asm("cvt.rna.tf32.f32 %0, %1;" : "=r"(u) : "f"(x));
    return __uint_as_float(u);
}

__device__ __forceinline__ uint32_t smem_u32(const void* p) {
    return (uint32_t)__cvta_generic_to_shared(p);
}

#define LDSM_X4(R0, R1, R2, R3, ADDR)                                          \
    asm volatile("ldmatrix.sync.aligned.m8n8.x4.shared.b16 {%0,%1,%2,%3}, [%4];" \
                 : "=r"(R0), "=r"(R1), "=r"(R2), "=r"(R3) : "r"(ADDR))

#define MMA_TF32(C, A, B0, B1)                                                  \
    asm volatile("mma.sync.aligned.m16n8k8.row.col.f32.tf32.tf32.f32 "          \
                 "{%0,%1,%2,%3}, {%4,%5,%6,%7}, {%8,%9}, {%0,%1,%2,%3};"        \
                 : "+f"((C)[0]), "+f"((C)[1]), "+f"((C)[2]), "+f"((C)[3])       \
                 : "r"((A)[0]), "r"((A)[1]), "r"((A)[2]), "r"((A)[3]),          \
                   "r"(B0), "r"(B1))

// ----------------------------------------------------------------------------
// TF32 tensor-core GEMM: C = alpha * A @ Bw^T (+bias+resid). 128x128 tile,
// BK=32, 256 threads, warp tile 64x32 (m16n8k8 atoms). Batched via blockIdx.z.
// streamC=1 -> __stcs (evict-first) stores for write-once outputs.
// ----------------------------------------------------------------------------
__global__ __launch_bounds__(256, 2)
void gemm_tf32(const float* __restrict__ A, const float* __restrict__ Bw,
               float* __restrict__ C,
               int K, int lda, int ldb, int ldc, float alpha,
               size_t sAb, size_t sAh, size_t sBb, size_t sBh, size_t sCz, int hdiv,
               const float* __restrict__ bias, const float* __restrict__ resid,
               int streamC)
{
    __shared__ float As[128][36];
    __shared__ float Bs[128][36];

    const int tid  = threadIdx.x;
    const int lane = tid & 31;
    const int wid  = tid >> 5;
    const int wm   = wid >> 2;
    const int wn   = wid & 3;
    const int rowBase = blockIdx.y * 128;
    const int colBase = blockIdx.x * 128;

    const int z  = blockIdx.z;
    const int zb = z / hdiv;
    const int zh = z - zb * hdiv;
    A  += (size_t)zb * sAb + (size_t)zh * sAh;
    Bw += (size_t)zb * sBb + (size_t)zh * sBh;
    C  += (size_t)z * sCz;

    int lrow[4], lcol[4];
    #pragma unroll
    for (int i = 0; i < 4; i++) {
        int f = tid + (i << 8);
        lrow[i] = f >> 3;
        lcol[i] = (f & 7) << 2;
    }

    const int arow = wm * 64 + (lane & 15);
    const int acol = (lane >> 4) << 2;
    uint32_t aAddr[4];
    #pragma unroll
    for (int mi = 0; mi < 4; mi++)
        aAddr[mi] = smem_u32(&As[arow + mi * 16][acol]);
    const int brow = wn * 32 + ((lane >> 4) << 3) + (lane & 7);
    const int bcol = ((lane >> 3) & 1) << 2;
    uint32_t bAddr[2];
    #pragma unroll
    for (int p = 0; p < 2; p++)
        bAddr[p] = smem_u32(&Bs[brow + p * 16][bcol]);

    float acc[4][4][4];
    #pragma unroll
    for (int mi = 0; mi < 4; mi++)
        #pragma unroll
        for (int ni = 0; ni < 4; ni++)
            #pragma unroll
            for (int r = 0; r < 4; r++) acc[mi][ni][r] = 0.f;

    float4 pa[4], pb[4];
    #pragma unroll
    for (int i = 0; i < 4; i++) {
        pa[i] = *reinterpret_cast<const float4*>(A  + (size_t)(rowBase + lrow[i]) * lda + lcol[i]);
        pb[i] = *reinterpret_cast<const float4*>(Bw + (size_t)(colBase + lrow[i]) * ldb + lcol[i]);
    }
    #pragma unroll
    for (int i = 0; i < 4; i++) {
        float* da = &As[lrow[i]][lcol[i]];
        da[0] = to_tf32(pa[i].x); da[1] = to_tf32(pa[i].y);
        da[2] = to_tf32(pa[i].z); da[3] = to_tf32(pa[i].w);
        float* db = &Bs[lrow[i]][lcol[i]];
        db[0] = to_tf32(pb[i].x); db[1] = to_tf32(pb[i].y);
        db[2] = to_tf32(pb[i].z); db[3] = to_tf32(pb[i].w);
    }
    __syncthreads();

    for (int k0 = 0; k0 < K; k0 += 32) {
        const bool has = (k0 + 32) < K;
        if (has) {
            #pragma unroll
            for (int i = 0; i < 4; i++) {
                pa[i] = *reinterpret_cast<const float4*>(A  + (size_t)(rowBase + lrow[i]) * lda + k0 + 32 + lcol[i]);
                pb[i] = *reinterpret_cast<const float4*>(Bw + (size_t)(colBase + lrow[i]) * ldb + k0 + 32 + lcol[i]);
            }
        }
        #pragma unroll
        for (int ks = 0; ks < 4; ks++) {
            const uint32_t koff = ks * 32;
            uint32_t a[4][4], b[2][4];
            #pragma unroll
            for (int mi = 0; mi < 4; mi++)
                LDSM_X4(a[mi][0], a[mi][1], a[mi][2], a[mi][3], aAddr[mi] + koff);
            #pragma unroll
            for (int p = 0; p < 2; p++)
                LDSM_X4(b[p][0], b[p][1], b[p][2], b[p][3], bAddr[p] + koff);
            #pragma unroll
            for (int mi = 0; mi < 4; mi++)
                #pragma unroll
                for (int ni = 0; ni < 4; ni++) {
                    const int p = ni >> 1, o = (ni & 1) << 1;
                    MMA_TF32(acc[mi][ni], a[mi], b[p][o], b[p][o + 1]);
                }
        }
        __syncthreads();
        if (has) {
            #pragma unroll
            for (int i = 0; i < 4; i++) {
                float* da = &As[lrow[i]][lcol[i]];
                da[0] = to_tf32(pa[i].x); da[1] = to_tf32(pa[i].y);
                da[2] = to_tf32(pa[i].z); da[3] = to_tf32(pa[i].w);
                float* db = &Bs[lrow[i]][lcol[i]];
                db[0] = to_tf32(pb[i].x); db[1] = to_tf32(pb[i].y);
                db[2] = to_tf32(pb[i].z); db[3] = to_tf32(pb[i].w);
            }
            __syncthreads();
        }
    }

    const int erow = rowBase + wm * 64 + (lane >> 2);
    const int ecol = colBase + wn * 32 + ((lane & 3) << 1);
    #pragma unroll
    for (int mi = 0; mi < 4; mi++) {
        #pragma unroll
        for (int ni = 0; ni < 4; ni++) {
            const int r = erow + mi * 16;
            const int c = ecol + ni * 8;
            float2 add = make_float2(0.f, 0.f);
            if (bias) {
                float2 bb = *reinterpret_cast<const float2*>(bias + c);
                add.x += bb.x; add.y += bb.y;
            }
            float2 v0, v1;
            v0.x = alpha * acc[mi][ni][0] + add.x;
            v0.y = alpha * acc[mi][ni][1] + add.y;
            v1.x = alpha * acc[mi][ni][2] + add.x;
            v1.y = alpha * acc[mi][ni][3] + add.y;
            if (resid) {
                float2 r0 = *reinterpret_cast<const float2*>(resid + (size_t)r * ldc + c);
                float2 r1 = *reinterpret_cast<const float2*>(resid + (size_t)(r + 8) * ldc + c);
                v0.x += r0.x; v0.y += r0.y;
                v1.x += r1.x; v1.y += r1.y;
            }
            float2* p0 = reinterpret_cast<float2*>(C + (size_t)r * ldc + c);
            float2* p1 = reinterpret_cast<float2*>(C + (size_t)(r + 8) * ldc + c);
            if (streamC) { __stcs(p0, v0); __stcs(p1, v1); }
            else         { *p0 = v0;       *p1 = v1;       }
        }
    }
}

// ----------------------------------------------------------------------------
// Top-k: 2 warps per score row (32 values/lane), block-shared per-row state.
//   1. max + sum(exp) (cross-warp via smem)
//   2. keys computed once in place; two-level 8-bit histogram (block-shared,
//      smem atomics) -> 16-bit threshold for the 20th value
//   3. collect candidates (~20-25); warp bitonic sort of packed 64-bit keys
//      (value desc, index asc) -> exact top-20; exact fallbacks beyond.
//   4. p = exp(v-m)/sum; sparse AV gather (2 warps split 64 dims) -> g_O
// ----------------------------------------------------------------------------
__device__ __forceinline__ uint32_t fkey(float f) {
    uint32_t u = __float_as_uint(f);
    return (u & 0x80000000u) ? ~u : (u | 0x80000000u);
}
__device__ __forceinline__ float fkey_inv(uint32_t k) {
    uint32_t u = (k & 0x80000000u) ? (k ^ 0x80000000u) : ~k;
    return __uint_as_float(u);
}

// find bin B with count(bins>B) < target <= count(bins>=B); returns cntAbove
__device__ __forceinline__ void hist_thresh(const int* h, int lane, int target,
                                            int& B, int& cntAbove)
{
    int c = 0;
    #pragma unroll
    for (int k = 0; k < 8; k++) c += h[lane * 8 + k];
    int S = c;
    #pragma unroll
    for (int off = 1; off < 32; off <<= 1) {
        int o = __shfl_down_sync(FULL, S, off);
        if (lane + off < 32) S += o;
    }
    int Snext = __shfl_down_sync(FULL, S, 1);
    if (lane == 31) Snext = 0;
    const bool isL = (S >= target) && (Snext < target);
    const unsigned ball = __ballot_sync(FULL, isL);
    const int L = __ffs(ball) - 1;
    int myB = 0, myC = 0;
    if (isL) {
        int cum = Snext;
        for (int bb = lane * 8 + 7; bb >= lane * 8; bb--) {
            if (cum + h[bb] >= target) { myB = bb; myC = cum; break; }
            cum += h[bb];
        }
    }
    B        = __shfl_sync(FULL, myB, L);
    cntAbove = __shfl_sync(FULL, myC, L);
}

__global__ __launch_bounds__(256)
void topk_av()
{
    __shared__ int      hist1[4][256];
    __shared__ int      hist2[4][256];
    __shared__ uint32_t candK[4][CAP];
    __shared__ int      candI[4][CAP];
    __shared__ int      cnt[4];
    __shared__ float    mxh[4][2];
    __shared__ float    smh[4][2];
    __shared__ float    topV[4][NTOPK];
    __shared__ int      topIx[4][NTOPK];

    const int tid  = threadIdx.x;
    const int lane = tid & 31;
    const int wid  = tid >> 5;
    const int pair = wid >> 1;             // row within block, 0..3
    const int half = wid & 1;              // which 1024-key half
    const int row  = blockIdx.x * 4 + pair;  // (b*H+h)*LQ + q
    const int q    = row & (NLQ - 1);
    const int bh   = row >> 9;
    const int h    = bh & (NH - 1);
    const int b    = bh >> 3;

    const float* s = g_S + (size_t)row * NLK + half * 1024;

    // ---- zero shared state ----
    #pragma unroll
    for (int i = 0; i < 4; i++) {
        (&hist1[0][0])[tid + (i << 8)] = 0;
        (&hist2[0][0])[tid + (i << 8)] = 0;
    }
    if (tid < 4) cnt[tid] = 0;

    // ---- load 32 values/lane, evict-first (S read once) ----
    float v[32];
    #pragma unroll
    for (int i = 0; i < 8; i++) {
        float4 t = __ldcs(reinterpret_cast<const float4*>(s + i * 128 + lane * 4));
        v[i * 4 + 0] = t.x; v[i * 4 + 1] = t.y;
        v[i * 4 + 2] = t.z; v[i * 4 + 3] = t.w;
    }

    // ---- half max -> combine across warps ----
    float m = v[0];
    #pragma unroll
    for (int i = 1; i < 32; i++) m = fmaxf(m, v[i]);
    #pragma unroll
    for (int off = 16; off > 0; off >>= 1)
        m = fmaxf(m, __shfl_xor_sync(FULL, m, off));
    if (lane == 0) mxh[pair][half] = m;
    __syncthreads();                                    // S1
    m = fmaxf(mxh[pair][0], mxh[pair][1]);

    // ---- half sum(exp) -> combine ----
    float ls = 0.f;
    #pragma unroll
    for (int i = 0; i < 32; i++) ls += __expf(v[i] - m);
    #pragma unroll
    for (int off = 16; off > 0; off >>= 1)
        ls += __shfl_xor_sync(FULL, ls, off);
    if (lane == 0) smh[pair][half] = ls;

    // ---- keys in place (computed ONCE) ----
    #pragma unroll
    for (int i = 0; i < 32; i++) v[i] = __uint_as_float(fkey(v[i]));

    // ---- level-1 histogram ----
    #pragma unroll
    for (int i = 0; i < 32; i++)
        atomicAdd(&hist1[pair][__float_as_uint(v[i]) >> 24], 1);
    __syncthreads();                                    // S2
    const float ssum = smh[pair][0] + smh[pair][1];

    int B1, cnt1;
    hist_thresh(hist1[pair], lane, NTOPK, B1, cnt1);

    // ---- level-2 histogram within bin B1 ----
    #pragma unroll
    for (int i = 0; i < 32; i++) {
        const uint32_t k = __float_as_uint(v[i]);
        if ((k >> 24) == (uint32_t)B1) atomicAdd(&hist2[pair][(k >> 16) & 0xff], 1);
    }
    __syncthreads();                                    // S3

    int B2, cnt2;
    hist_thresh(hist2[pair], lane, NTOPK - cnt1, B2, cnt2);
    const uint32_t T16 = ((uint32_t)B1 << 8) | (uint32_t)B2;

    // ---- collect candidates (count >= 20 guaranteed by construction) ----
    #pragma unroll
    for (int i = 0; i < 32; i++) {
        const uint32_t k = __float_as_uint(v[i]);
        if ((k >> 16) >= T16) {
            const int p = atomicAdd(&cnt[pair], 1);
            if (p < CAP) {
                candK[pair][p] = k;
                candI[pair][p] = half * 1024 + (i >> 2) * 128 + (lane << 2) + (i & 3);
            }
        }
    }
    __syncthreads();                                    // S4
    const int n = cnt[pair];

    // ---- pathological overflow (n > CAP): each warp selects its half's
    //      exact top-20 from registers into candK[0..40), then merge ----
    if (n > CAP) {
        for (int t = 0; t < NTOPK; t++) {
            uint32_t bk = 0; int bi = 0x7fffffff; int bs = -1;
            #pragma unroll
            for (int i = 0; i < 32; i++) {
                const uint32_t k = __float_as_uint(v[i]);
                const int idx = half * 1024 + (i >> 2) * 128 + (lane << 2) + (i & 3);
                if (k > bk || (k == bk && idx < bi)) { bk = k; bi = idx; bs = i; }
            }
            const int myBi = bi;
            #pragma unroll
            for (int off = 16; off > 0; off >>= 1) {
                const uint32_t ok = __shfl_xor_sync(FULL, bk, off);
                const int      oi = __shfl_xor_sync(FULL, bi, off);
                if (ok > bk || (ok == bk && oi < bi)) { bk = ok; bi = oi; }
            }
            if (myBi == bi && bs >= 0) {
                #pragma unroll
                for (int i = 0; i < 32; i++) if (i == bs) v[i] = __uint_as_float(0u);
            }
            if (lane == 0) { candK[pair][half * NTOPK + t] = bk; candI[pair][half * NTOPK + t] = bi; }
        }
    }
    __syncthreads();                                    // S5

    // ---- exact final selection (warp half==0 of each pair) ----
    if (half == 0) {
        const int nSel = (n > CAP) ? (2 * NTOPK) : n;
        if (nSel <= 32) {
            // warp bitonic sort of packed keys (val desc, idx asc)
            unsigned long long key = 0ULL;
            if (lane < nSel)
                key = ((unsigned long long)candK[pair][lane] << 32)
                    | (uint32_t)(~candI[pair][lane]);
            #pragma unroll
            for (int k = 2; k <= 32; k <<= 1) {
                #pragma unroll
                for (int j = k >> 1; j > 0; j >>= 1) {
                    const unsigned long long o = __shfl_xor_sync(FULL, key, j);
                    const bool dirDesc = ((lane & k) == 0);
                    const bool lower   = ((lane & j) == 0);
                    const bool keepMax = (dirDesc == lower);
                    key = keepMax ? (key > o ? key : o) : (key < o ? key : o);
                }
            }
            if (lane < NTOPK) {
                topV[pair][lane]  = fkey_inv((uint32_t)(key >> 32));
                topIx[pair][lane] = (int)(~(uint32_t)key);
            }
        } else {
            // serial exact 20x argmax over smem candidates
            for (int t = 0; t < NTOPK; t++) {
                uint32_t bk = 0; int bi = 0x7fffffff; int bp = -1;
                for (int p = lane; p < nSel; p += 32) {
                    const uint32_t xk = candK[pair][p];
                    const int      xi = candI[pair][p];
                    if (xk > bk || (xk == bk && xi < bi)) { bk = xk; bi = xi; bp = p; }
                }
                #pragma unroll
                for (int off = 16; off > 0; off >>= 1) {
                    const uint32_t ok = __shfl_xor_sync(FULL, bk, off);
                    const int      oi = __shfl_xor_sync(FULL, bi, off);
                    const int      op = __shfl_xor_sync(FULL, bp, off);
                    if (ok > bk || (ok == bk && oi < bi)) { bk = ok; bi = oi; bp = op; }
                }
                if (lane == 0) {
                    topV[pair][t]  = fkey_inv(bk);
                    topIx[pair][t] = bi;
                    candK[pair][bp] = 0;
                }
                __syncwarp();
            }
        }
    }
    __syncthreads();                                    // S6

    // ---- probs + sparse AV (both warps: 32 dims each) ----
    const float p  = (lane < NTOPK) ? __expf(topV[pair][lane] - m) / ssum : 0.f;
    const int   ix = (lane < NTOPK) ? topIx[pair][lane] : 0;
    const float* Vg = g_V + (size_t)b * NLK * NE + h * NHD + half * 32 + lane;
    float a = 0.f;
    #pragma unroll
    for (int j = 0; j < NTOPK; j++) {
        const float pj = __shfl_sync(FULL, p, j);
        const int   ij = __shfl_sync(FULL, ix, j);
        a = fmaf(pj, Vg[(size_t)ij * NE], a);
    }
    g_O[(size_t)(b * NLQ + q) * NE + h * NHD + half * 32 + lane] = a;
}

// ----------------------------------------------------------------------------
extern "C" void kernel_launch(void* const* d_in, const int* in_sizes, int n_in,
                              void* d_out, int out_size)
{
    const float* q  = (const float*)d_in[0];
    const float* k  = (const float*)d_in[1];
    const float* v  = (const float*)d_in[2];
    const float* Wq = (const float*)d_in[3];
    const float* Wk = (const float*)d_in[4];
    const float* Wv = (const float*)d_in[5];
    const float* Wo = (const float*)d_in[6];
    const float* bo = (const float*)d_in[7];
    float* out = (float*)d_out;

    float *gQ, *gK, *gV, *gS, *gO;
    cudaGetSymbolAddress((void**)&gQ, g_Q);
    cudaGetSymbolAddress((void**)&gK, g_K);
    cudaGetSymbolAddress((void**)&gV, g_V);
    cudaGetSymbolAddress((void**)&gS, g_S);
    cudaGetSymbolAddress((void**)&gO, g_O);

    dim3 blk(256);

    // Q = q @ Wq^T
    gemm_tf32<<<dim3(NE / 128, (NB * NLQ) / 128, 1), blk>>>(
        q, Wq, gQ, NE, NE, NE, NE, 1.0f,
        0, 0, 0, 0, 0, 1, nullptr, nullptr, 0);

    // K = k @ Wk^T
    gemm_tf32<<<dim3(NE / 128, (NB * NLK) / 128, 1), blk>>>(
        k, Wk, gK, NE, NE, NE, NE, 1.0f,
        0, 0, 0, 0, 0, 1, nullptr, nullptr, 0);

    // V = v @ Wv^T
    gemm_tf32<<<dim3(NE / 128, (NB * NLK) / 128, 1), blk>>>(
        v, Wv, gV, NE, NE, NE, NE, 1.0f,
        0, 0, 0, 0, 0, 1, nullptr, nullptr, 0);

    // S[b,h] = (1/8) * Q_h @ K_h^T  (streaming stores: written once, read once)
    gemm_tf32<<<dim3(NLK / 128, NLQ / 128, NB * NH), blk>>>(
        gQ, gK, gS, NHD, NE, NE, NLK, 0.125f,
        (size_t)NLQ * NE, (size_t)NHD,
        (size_t)NLK * NE, (size_t)NHD,
        (size_t)NLQ * NLK, NH,
        nullptr, nullptr, 1);

    // 2-warps-per-row radix top-20 + softmax + sparse AV
    topk_av<<<(NB * NH * NLQ) / 4, blk>>>();

    // out = O @ Wo^T + bo + q
    gemm_tf32<<<dim3(NE / 128, (NB * NLQ) / 128, 1), blk>>>(
        gO, Wo, out, NE, NE, NE, NE, 1.0f,
        0, 0, 0, 0, 0, 1, bo, q, 0);
}